// round 14
// baseline (speedup 1.0000x reference)
#include <cuda_runtime.h>
#include <cuda_fp16.h>
#include <cstdint>
#include <math.h>

// ---------------- problem constants ----------------
#define BATCH 16
#define TOK   1280
#define CH    512
#define NHEAD 8
#define HDIM  64
#define NLAYER 6
#define FFDIM 2048
#define MROWS (BATCH*TOK)    // 20480

typedef __half f16;

// ---------------- device scratch ----------------
__device__ float g_x [MROWS*CH];
__device__ f16  g_qh[MROWS*CH], g_ql[MROWS*CH];
__device__ f16  g_k [MROWS*CH];
__device__ f16  g_v [MROWS*CH];
__device__ f16  g_hh [MROWS*CH],   g_hl [MROWS*CH];
__device__ f16  g_yh [MROWS*CH],   g_yl [MROWS*CH];
__device__ f16  g_ffh[MROWS*FFDIM], g_ffl[MROWS*FFDIM];
// weights (single fp16)
__device__ f16 g_wq[NLAYER*CH*CH];
__device__ f16 g_wk[NLAYER*CH*CH];
__device__ f16 g_wv[NLAYER*CH*CH];
__device__ f16 g_wo[NLAYER*CH*CH];
__device__ f16 g_w1[NLAYER*CH*FFDIM];
__device__ f16 g_w2[NLAYER*FFDIM*CH];

// ---------------- helpers ----------------
__device__ __forceinline__ uint32_t smem_u32(const void* p) {
    uint32_t a;
    asm("{ .reg .u64 t; cvta.to.shared.u64 t, %1; cvt.u32.u64 %0, t; }"
        : "=r"(a) : "l"(p));
    return a;
}
// pack: low 16 = x0, high 16 = x1
__device__ __forceinline__ uint32_t pk_f16(float x0, float x1) {
    __half2 h = __floats2half2_rn(x0, x1);
    return *reinterpret_cast<uint32_t*>(&h);
}
__device__ __forceinline__ float f16_lo(uint32_t u) {
    __half2 h = *reinterpret_cast<__half2*>(&u);
    return __low2float(h);
}
__device__ __forceinline__ float f16_hi(uint32_t u) {
    __half2 h = *reinterpret_cast<__half2*>(&u);
    return __high2float(h);
}

__device__ __forceinline__ void cpasync16(uint32_t dst, const void* src) {
    asm volatile("cp.async.cg.shared.global [%0], [%1], 16;" :: "r"(dst), "l"(src));
}
__device__ __forceinline__ void cp_commit() {
    asm volatile("cp.async.commit_group;" ::: "memory");
}
__device__ __forceinline__ void cp_wait1() {
    asm volatile("cp.async.wait_group 1;" ::: "memory");
}
__device__ __forceinline__ void cp_wait0() {
    asm volatile("cp.async.wait_group 0;" ::: "memory");
}
__device__ __forceinline__ void ldsm4(uint32_t* r, uint32_t addr) {
    asm volatile("ldmatrix.sync.aligned.m8n8.x4.shared.b16 {%0,%1,%2,%3}, [%4];"
                 : "=r"(r[0]), "=r"(r[1]), "=r"(r[2]), "=r"(r[3]) : "r"(addr));
}
__device__ __forceinline__ void ldsm4t(uint32_t* r, uint32_t addr) {
    asm volatile("ldmatrix.sync.aligned.m8n8.x4.trans.shared.b16 {%0,%1,%2,%3}, [%4];"
                 : "=r"(r[0]), "=r"(r[1]), "=r"(r[2]), "=r"(r[3]) : "r"(addr));
}
__device__ __forceinline__ void mma16816(float* d, const uint32_t* a, const uint32_t* b) {
    asm volatile(
        "mma.sync.aligned.m16n8k16.row.col.f32.f16.f16.f32 "
        "{%0,%1,%2,%3}, {%4,%5,%6,%7}, {%8,%9}, {%0,%1,%2,%3};"
        : "+f"(d[0]), "+f"(d[1]), "+f"(d[2]), "+f"(d[3])
        : "r"(a[0]), "r"(a[1]), "r"(a[2]), "r"(a[3]), "r"(b[0]), "r"(b[1]));
}

// ---------------- weight convert: fp32 -> fp16 ----------------
__global__ void wcvt_kernel(const float* __restrict__ w,
                            f16* __restrict__ o, int n)
{
    int i = (blockIdx.x * blockDim.x + threadIdx.x) * 4;
    if (i >= n) return;
    float4 v = *(const float4*)(w + i);
    uint2 ho = {pk_f16(v.x, v.y), pk_f16(v.z, v.w)};
    *(uint2*)(o + i) = ho;
}

// ---------------- HMMA fp16 2-pass GEMM: 128x128 tile, 3-stage pipeline --------
// 8 warps 4(M)x2(N), warp tile 32x64, BK=32, one __syncthreads per chunk.
// D = (Ah + Al) @ Bh ; A split fp16 (22-bit), B single fp16.
#define APITCH 40
#define BPITCH 136
#define STG_A  10240          // 128*80 B
#define STG_B  8704           // 32*272 B
#define STG    (2*STG_A + STG_B)     // 29184 per stage (Ah, Al, Bh)
#define SOFF_AL STG_A
#define SOFF_BH (2*STG_A)
#define GEMM_SMEM (3*STG)     // 87552 B

// OUT: 0 = fp32 out (+RES optional), 1 = fp16 hi/lo split, 2 = fp16 single
template<int ACT, bool RES, int OUT>
__device__ __forceinline__ void gemm_body(
    const f16* __restrict__ Ahg, const f16* __restrict__ Alg,
    const f16* __restrict__ Bhg,
    const float* __restrict__ bias, const float* __restrict__ res,
    float* __restrict__ out, f16* __restrict__ outh, f16* __restrict__ outl,
    int N, int K, int m0, int n0)
{
    extern __shared__ char dynsm[];
    const uint32_t sb  = smem_u32(dynsm);

    const int tid  = threadIdx.x;
    const int lane = tid & 31, wid = tid >> 5;
    const int wm = wid >> 1, wn = wid & 1;

    const int lq = lane >> 3, lr = lane & 7;
    const uint32_t aOff = ((wm * 32 + (lq & 1) * 8 + lr) * APITCH + (lq >> 1) * 8) * 2;
    const uint32_t bOff = (((lq & 1) * 8 + lr) * BPITCH + wn * 64 + (lq >> 1) * 8) * 2;

    float acc[2][8][4];
#pragma unroll
    for (int i = 0; i < 2; i++)
#pragma unroll
        for (int j = 0; j < 8; j++)
#pragma unroll
            for (int c = 0; c < 4; c++) acc[i][j][c] = 0.f;

    const int nch = K >> 5;

    auto stage = [&](int ch, int st) {
        const int k0 = ch << 5;
        const uint32_t base = sb + st * STG;
#pragma unroll
        for (int i = 0; i < 2; i++) {
            int sid = tid + i * 256;
            int row = sid >> 2, sg = sid & 3;
            uint32_t d = base + row * 80 + sg * 16;
            size_t  g = (size_t)(m0 + row) * K + k0 + sg * 8;
            cpasync16(d,           Ahg + g);
            cpasync16(d + SOFF_AL, Alg + g);
        }
#pragma unroll
        for (int i = 0; i < 2; i++) {
            int sid = tid + i * 256;
            int row = sid >> 4, sg = sid & 15;
            uint32_t d = base + SOFF_BH + row * 272 + sg * 16;
            size_t  g = (size_t)(k0 + row) * N + n0 + sg * 8;
            cpasync16(d, Bhg + g);
        }
    };

    stage(0, 0);
    cp_commit();
    stage(1, 1);
    cp_commit();

    int st2 = 2;
    for (int ch = 0; ch < nch; ch++) {
        if (ch + 1 < nch) cp_wait1(); else cp_wait0();
        __syncthreads();
        if (ch + 2 < nch) {
            stage(ch + 2, st2);
            cp_commit();
            st2 = (st2 == 2) ? 0 : st2 + 1;
        }

        const uint32_t base = sb + (ch % 3) * STG;
        const uint32_t bAh = base, bAl = base + SOFF_AL;
        const uint32_t bBh = base + SOFF_BH;
#pragma unroll
        for (int s = 0; s < 2; s++) {
            uint32_t ah[2][4], al[2][4], b[8][2];
#pragma unroll
            for (int im = 0; im < 2; im++) {
                uint32_t d = (im * 16 * APITCH + s * 16) * 2;
                ldsm4(ah[im], bAh + aOff + d);
                ldsm4(al[im], bAl + aOff + d);
            }
#pragma unroll
            for (int jp = 0; jp < 4; jp++) {
                uint32_t tmp[4];
                ldsm4t(tmp, bBh + bOff + (s * 16 * BPITCH + jp * 16) * 2);
                b[2*jp][0] = tmp[0]; b[2*jp][1] = tmp[1];
                b[2*jp+1][0] = tmp[2]; b[2*jp+1][1] = tmp[3];
            }
#pragma unroll
            for (int im = 0; im < 2; im++)
#pragma unroll
                for (int jn = 0; jn < 8; jn++) mma16816(acc[im][jn], ah[im], b[jn]);
#pragma unroll
            for (int im = 0; im < 2; im++)
#pragma unroll
                for (int jn = 0; jn < 8; jn++) mma16816(acc[im][jn], al[im], b[jn]);
        }
    }

    const int gr = lane >> 2, gc = lane & 3;
#pragma unroll
    for (int im = 0; im < 2; im++) {
        int r0 = m0 + wm * 32 + im * 16 + gr;
#pragma unroll
        for (int jn = 0; jn < 8; jn++) {
            int c = n0 + wn * 64 + jn * 8 + gc * 2;
            float2 bv = *(const float2*)(bias + c);
            float v00 = acc[im][jn][0] + bv.x;
            float v01 = acc[im][jn][1] + bv.y;
            float v10 = acc[im][jn][2] + bv.x;
            float v11 = acc[im][jn][3] + bv.y;
            if (ACT == 1) {
                v00 = fmaxf(v00, 0.f); v01 = fmaxf(v01, 0.f);
                v10 = fmaxf(v10, 0.f); v11 = fmaxf(v11, 0.f);
            }
            if (RES) {
                float2 ra = *(const float2*)(res + (size_t)r0 * N + c);
                float2 rb = *(const float2*)(res + (size_t)(r0 + 8) * N + c);
                v00 += ra.x; v01 += ra.y; v10 += rb.x; v11 += rb.y;
            }
            if (OUT == 1) {
                uint32_t h0 = pk_f16(v00, v01);
                uint32_t h1 = pk_f16(v10, v11);
                uint32_t l0 = pk_f16(v00 - f16_lo(h0), v01 - f16_hi(h0));
                uint32_t l1 = pk_f16(v10 - f16_lo(h1), v11 - f16_hi(h1));
                *(uint32_t*)(outh + (size_t)r0 * N + c)       = h0;
                *(uint32_t*)(outh + (size_t)(r0 + 8) * N + c) = h1;
                *(uint32_t*)(outl + (size_t)r0 * N + c)       = l0;
                *(uint32_t*)(outl + (size_t)(r0 + 8) * N + c) = l1;
            } else if (OUT == 2) {
                *(uint32_t*)(outh + (size_t)r0 * N + c)       = pk_f16(v00, v01);
                *(uint32_t*)(outh + (size_t)(r0 + 8) * N + c) = pk_f16(v10, v11);
            } else {
                float2 o0 = {v00, v01}, o1 = {v10, v11};
                *(float2*)(out + (size_t)r0 * N + c)       = o0;
                *(float2*)(out + (size_t)(r0 + 8) * N + c) = o1;
            }
        }
    }
}

template<int ACT, bool RES, int OUT>
__global__ void __launch_bounds__(256, 2) gemm_mma(
    const f16* __restrict__ Ahg, const f16* __restrict__ Alg,
    const f16* __restrict__ Bhg,
    const float* __restrict__ bias, const float* __restrict__ res,
    float* __restrict__ out, f16* __restrict__ outh, f16* __restrict__ outl,
    int N, int K)
{
    gemm_body<ACT, RES, OUT>(Ahg, Alg, Bhg, bias, res, out, outh, outl,
                             N, K, blockIdx.y * 128, blockIdx.x * 128);
}

// fused QKV: blockIdx.x in [0,12): matrix = x>>2, n-tile = x&3
// q -> split hi/lo; k, v -> single fp16
__global__ void __launch_bounds__(256, 2) qkv_mma(
    const f16* __restrict__ Ahg, const f16* __restrict__ Alg,
    const f16* __restrict__ Bq, const f16* __restrict__ Bk, const f16* __restrict__ Bv,
    const float* __restrict__ c0, const float* __restrict__ c1,
    const float* __restrict__ c2,
    f16* __restrict__ oqh, f16* __restrict__ oql,
    f16* __restrict__ ok, f16* __restrict__ ov)
{
    int mat = blockIdx.x >> 2;
    int m0 = blockIdx.y * 128, n0 = (blockIdx.x & 3) * 128;
    if (mat == 0) {
        gemm_body<0, false, 1>(Ahg, Alg, Bq, c0, nullptr, nullptr, oqh, oql,
                               CH, CH, m0, n0);
    } else if (mat == 1) {
        gemm_body<0, false, 2>(Ahg, Alg, Bk, c1, nullptr, nullptr, ok, nullptr,
                               CH, CH, m0, n0);
    } else {
        gemm_body<0, false, 2>(Ahg, Alg, Bv, c2, nullptr, nullptr, ov, nullptr,
                               CH, CH, m0, n0);
    }
}

// ---------------- embed ----------------
__global__ void embed_kernel(const float* __restrict__ img,
                             const float* __restrict__ rad,
                             const float* __restrict__ pos)
{
    int idx = blockIdx.x * blockDim.x + threadIdx.x;
    int c   = idx & (CH - 1);
    int row = idx >> 9;
    int b   = row / TOK;
    int t   = row - b * TOK;
    float v;
    if (t < 1024) v = img[(size_t)(b * CH + c) * 1024 + t];
    else          v = rad[(size_t)(b * CH + c) * 256  + (t - 1024)];
    g_x[idx] = v + pos[t * CH + c];
}

// ---------------- layernorm -> fp16 hi/lo ----------------
__global__ void ln_kernel(const float* __restrict__ x,
                          f16* __restrict__ oh, f16* __restrict__ ol,
                          const float* __restrict__ w, const float* __restrict__ bb)
{
    int warp = threadIdx.x >> 5, lane = threadIdx.x & 31;
    int row  = blockIdx.x * 8 + warp;
    const float4* xr = (const float4*)(x + (size_t)row * CH);
    float4 v[4];
    float s = 0.f, s2 = 0.f;
#pragma unroll
    for (int i = 0; i < 4; i++) {
        v[i] = xr[lane + 32 * i];
        s  += v[i].x + v[i].y + v[i].z + v[i].w;
        s2 += v[i].x*v[i].x + v[i].y*v[i].y + v[i].z*v[i].z + v[i].w*v[i].w;
    }
#pragma unroll
    for (int off = 16; off; off >>= 1) {
        s  += __shfl_xor_sync(0xffffffffu, s,  off);
        s2 += __shfl_xor_sync(0xffffffffu, s2, off);
    }
    float m   = s * (1.f / CH);
    float inv = rsqrtf(s2 * (1.f / CH) - m * m + 1e-5f);
    const float4* wr = (const float4*)w;
    const float4* br = (const float4*)bb;
#pragma unroll
    for (int i = 0; i < 4; i++) {
        float4 wv = wr[lane + 32 * i], bv = br[lane + 32 * i];
        float o0 = (v[i].x - m) * inv * wv.x + bv.x;
        float o1 = (v[i].y - m) * inv * wv.y + bv.y;
        float o2 = (v[i].z - m) * inv * wv.z + bv.z;
        float o3 = (v[i].w - m) * inv * wv.w + bv.w;
        uint32_t h0 = pk_f16(o0, o1), h1 = pk_f16(o2, o3);
        uint32_t l0 = pk_f16(o0 - f16_lo(h0), o1 - f16_hi(h0));
        uint32_t l1 = pk_f16(o2 - f16_lo(h1), o3 - f16_hi(h1));
        size_t off = (size_t)row * CH + (lane + 32 * i) * 4;
        uint2 hh = {h0, h1}, ll = {l0, l1};
        *(uint2*)(oh + off) = hh;
        *(uint2*)(ol + off) = ll;
    }
}

// ---------------- final LN + scatter ----------------
__global__ void lnf_kernel(const float* __restrict__ x, float* __restrict__ out,
                           const float* __restrict__ w, const float* __restrict__ bb)
{
    int warp = threadIdx.x >> 5, lane = threadIdx.x & 31;
    int row  = blockIdx.x * 8 + warp;
    const float4* xr = (const float4*)(x + (size_t)row * CH);
    float4 v[4];
    float s = 0.f, s2 = 0.f;
#pragma unroll
    for (int i = 0; i < 4; i++) {
        v[i] = xr[lane + 32 * i];
        s  += v[i].x + v[i].y + v[i].z + v[i].w;
        s2 += v[i].x*v[i].x + v[i].y*v[i].y + v[i].z*v[i].z + v[i].w*v[i].w;
    }
#pragma unroll
    for (int off = 16; off; off >>= 1) {
        s  += __shfl_xor_sync(0xffffffffu, s,  off);
        s2 += __shfl_xor_sync(0xffffffffu, s2, off);
    }
    float m   = s * (1.f / CH);
    float inv = rsqrtf(s2 * (1.f / CH) - m * m + 1e-5f);
    int b = row / TOK, t = row - b * TOK;
    float* dst;
    if (t < 1024) dst = out + ((size_t)b * 1024 + t) * CH;
    else          dst = out + (size_t)BATCH*1024*CH + ((size_t)b*256 + (t-1024))*CH;
    const float4* wr = (const float4*)w;
    const float4* br = (const float4*)bb;
    float4* orow = (float4*)dst;
#pragma unroll
    for (int i = 0; i < 4; i++) {
        float4 wv = wr[lane + 32 * i], bv = br[lane + 32 * i], ov;
        ov.x = (v[i].x - m) * inv * wv.x + bv.x;
        ov.y = (v[i].y - m) * inv * wv.y + bv.y;
        ov.z = (v[i].z - m) * inv * wv.z + bv.z;
        ov.w = (v[i].w - m) * inv * wv.w + bv.w;
        orow[lane + 32 * i] = ov;
    }
}

// ---------------- MMA flash attention, fp16 2-pass ----------------
// CTA: 128 Q rows (8 warps x m16), KV tiles of 64 (double-buffered single-fp16).
// smem: Qh/Ql [128][72], K [2][64][72], V [2][64][72].
#define ATP 72
#define AT_QBYTES  18432
#define AT_KVB     9216
#define AT_OFF_KV  (2*AT_QBYTES)
#define ATTN_SMEM  (2*AT_QBYTES + 4*AT_KVB)   // 73728

__global__ void __launch_bounds__(256, 3) attn_mma(
    const f16* __restrict__ qh, const f16* __restrict__ ql,
    const f16* __restrict__ kg, const f16* __restrict__ vg,
    f16* __restrict__ yh, f16* __restrict__ yl)
{
    extern __shared__ char asm8[];
    const uint32_t sb = smem_u32(asm8);
    const int tid = threadIdx.x;
    const int lane = tid & 31, wid = tid >> 5;
    const int q0 = blockIdx.x * 128;
    const int h  = blockIdx.y;
    const int bz = blockIdx.z;
    const size_t gbase = (size_t)bz * TOK * CH + h * HDIM;

    // stage Q hi/lo (2048 slots / 256 thr = 8 iters)
#pragma unroll
    for (int i = 0; i < 8; i++) {
        int sid = tid + i * 256;
        int arr = sid >> 10;             // 0=hi, 1=lo
        int row = (sid >> 3) & 127;
        int sg  = sid & 7;
        const f16* src = (arr ? ql : qh) + gbase + (size_t)(q0 + row) * CH + sg * 8;
        cpasync16(sb + arr * AT_QBYTES + row * 144 + sg * 16, src);
    }

    auto stageKV = [&](int it, int bu) {
        const int k0 = it * 64;
#pragma unroll
        for (int i = 0; i < 4; i++) {
            int sid = tid + i * 256;
            int arr = sid >> 9;          // 0=K, 1=V
            int row = (sid >> 3) & 63;
            int sg  = sid & 7;
            const f16* base = arr ? vg : kg;
            cpasync16(sb + AT_OFF_KV + arr * (2 * AT_KVB) + bu * AT_KVB + row * 144 + sg * 16,
                      base + gbase + (size_t)(k0 + row) * CH + sg * 8);
        }
    };

    stageKV(0, 0);
    cp_commit();

    const int lq = lane >> 3, lr = lane & 7;
    const uint32_t aQ = ((wid * 16 + (lq & 1) * 8 + lr) * ATP + (lq >> 1) * 8) * 2;
    const uint32_t kRC = (((lq >> 1) * 8 + lr) * ATP + (lq & 1) * 8) * 2;
    const uint32_t vRC = (((lq & 1) * 8 + lr) * ATP + (lq >> 1) * 8) * 2;

    float of[8][4];
#pragma unroll
    for (int j = 0; j < 8; j++)
#pragma unroll
        for (int c = 0; c < 4; c++) of[j][c] = 0.f;
    float m0 = -1e30f, m1 = -1e30f, l0 = 0.f, l1 = 0.f;

    for (int it = 0; it < 20; it++) {
        const int bu = it & 1;
        if (it + 1 < 20) {
            stageKV(it + 1, bu ^ 1);
            cp_commit();
            cp_wait1();
        } else {
            cp_wait0();
        }
        __syncthreads();

        const uint32_t uK = sb + AT_OFF_KV + bu * AT_KVB;
        const uint32_t uV = sb + AT_OFF_KV + 2 * AT_KVB + bu * AT_KVB;

        // ---- S = Q K^T (2 passes: Qh, Ql vs Kh) ----
        float sf[8][4];
#pragma unroll
        for (int j = 0; j < 8; j++)
#pragma unroll
            for (int c = 0; c < 4; c++) sf[j][c] = 0.f;
#pragma unroll
        for (int s = 0; s < 4; s++) {
            uint32_t aH[4], aL[4];
            ldsm4(aH, sb + aQ + s * 32);
            ldsm4(aL, sb + AT_QBYTES + aQ + s * 32);
#pragma unroll
            for (int ng = 0; ng < 4; ng++) {
                uint32_t koff = kRC + (ng * 16 * ATP + s * 16) * 2;
                uint32_t kb[4];
                ldsm4(kb, uK + koff);
                mma16816(sf[2*ng],   aH, kb);
                mma16816(sf[2*ng+1], aH, kb + 2);
                mma16816(sf[2*ng],   aL, kb);
                mma16816(sf[2*ng+1], aL, kb + 2);
            }
        }

        // ---- online softmax on fragments ----
        float mloc0 = -1e30f, mloc1 = -1e30f;
#pragma unroll
        for (int j = 0; j < 8; j++) {
#pragma unroll
            for (int c = 0; c < 4; c++) sf[j][c] *= 0.125f;
            mloc0 = fmaxf(mloc0, fmaxf(sf[j][0], sf[j][1]));
            mloc1 = fmaxf(mloc1, fmaxf(sf[j][2], sf[j][3]));
        }
        mloc0 = fmaxf(mloc0, __shfl_xor_sync(0xffffffffu, mloc0, 1));
        mloc0 = fmaxf(mloc0, __shfl_xor_sync(0xffffffffu, mloc0, 2));
        mloc1 = fmaxf(mloc1, __shfl_xor_sync(0xffffffffu, mloc1, 1));
        mloc1 = fmaxf(mloc1, __shfl_xor_sync(0xffffffffu, mloc1, 2));
        float mn0 = fmaxf(m0, mloc0), mn1 = fmaxf(m1, mloc1);
        float al0 = __expf(m0 - mn0), al1 = __expf(m1 - mn1);
        m0 = mn0; m1 = mn1;

        uint32_t php[8], php2[8], plp[8], plp2[8];
        float sum0 = 0.f, sum1 = 0.f;
#pragma unroll
        for (int j = 0; j < 8; j++) {
            float p0 = __expf(sf[j][0] - m0);
            float p1 = __expf(sf[j][1] - m0);
            float p2 = __expf(sf[j][2] - m1);
            float p3 = __expf(sf[j][3] - m1);
            sum0 += p0 + p1; sum1 += p2 + p3;
            uint32_t h0 = pk_f16(p0, p1), h1 = pk_f16(p2, p3);
            php[j]  = h0;  php2[j] = h1;
            plp[j]  = pk_f16(p0 - f16_lo(h0), p1 - f16_hi(h0));
            plp2[j] = pk_f16(p2 - f16_lo(h1), p3 - f16_hi(h1));
        }
        sum0 += __shfl_xor_sync(0xffffffffu, sum0, 1);
        sum0 += __shfl_xor_sync(0xffffffffu, sum0, 2);
        sum1 += __shfl_xor_sync(0xffffffffu, sum1, 1);
        sum1 += __shfl_xor_sync(0xffffffffu, sum1, 2);
        l0 = l0 * al0 + sum0;
        l1 = l1 * al1 + sum1;
#pragma unroll
        for (int j = 0; j < 8; j++) {
            of[j][0] *= al0; of[j][1] *= al0;
            of[j][2] *= al1; of[j][3] *= al1;
        }

        // ---- O += P V (2 passes: Ph, Pl vs Vh) ----
#pragma unroll
        for (int t = 0; t < 4; t++) {
            uint32_t aPh[4] = {php[2*t], php2[2*t], php[2*t+1], php2[2*t+1]};
            uint32_t aPl[4] = {plp[2*t], plp2[2*t], plp[2*t+1], plp2[2*t+1]};
#pragma unroll
            for (int jp = 0; jp < 4; jp++) {
                uint32_t voff = vRC + (t * 16 * ATP + jp * 16) * 2;
                uint32_t vb[4];
                ldsm4t(vb, uV + voff);
                mma16816(of[2*jp],   aPh, vb);
                mma16816(of[2*jp+1], aPh, vb + 2);
                mma16816(of[2*jp],   aPl, vb);
                mma16816(of[2*jp+1], aPl, vb + 2);
            }
        }
        __syncthreads();
    }

    // ---- epilogue: O /= l, write y fp16 hi/lo ----
    const int gr = lane >> 2, gc = lane & 3;
    const float inv0 = 1.f / l0, inv1 = 1.f / l1;
    const size_t rA = gbase + (size_t)(q0 + wid * 16 + gr) * CH;
    const size_t rB = rA + (size_t)8 * CH;
#pragma unroll
    for (int j = 0; j < 8; j++) {
        float o0 = of[j][0] * inv0, o1 = of[j][1] * inv0;
        float o2 = of[j][2] * inv1, o3 = of[j][3] * inv1;
        uint32_t h0 = pk_f16(o0, o1), h1 = pk_f16(o2, o3);
        uint32_t lo0 = pk_f16(o0 - f16_lo(h0), o1 - f16_hi(h0));
        uint32_t lo1 = pk_f16(o2 - f16_lo(h1), o3 - f16_hi(h1));
        int c = j * 8 + gc * 2;
        *(uint32_t*)(yh + rA + c) = h0;
        *(uint32_t*)(yl + rA + c) = lo0;
        *(uint32_t*)(yh + rB + c) = h1;
        *(uint32_t*)(yl + rB + c) = lo1;
    }
}

// ---------------- orchestration ----------------
extern "C" void kernel_launch(void* const* d_in, const int* in_sizes, int n_in,
                              void* d_out, int out_size)
{
    const float* img  = (const float*)d_in[0];
    const float* rad  = (const float*)d_in[1];
    const float* pos  = (const float*)d_in[2];
    const float* ln1w = (const float*)d_in[3];
    const float* ln1b = (const float*)d_in[4];
    const float* Wq   = (const float*)d_in[5];
    const float* bq   = (const float*)d_in[6];
    const float* Wk   = (const float*)d_in[7];
    const float* bk   = (const float*)d_in[8];
    const float* Wv   = (const float*)d_in[9];
    const float* bv   = (const float*)d_in[10];
    const float* Wo   = (const float*)d_in[11];
    const float* bo   = (const float*)d_in[12];
    const float* ln2w = (const float*)d_in[13];
    const float* ln2b = (const float*)d_in[14];
    const float* W1   = (const float*)d_in[15];
    const float* b1   = (const float*)d_in[16];
    const float* W2   = (const float*)d_in[17];
    const float* b2   = (const float*)d_in[18];
    const float* lnfw = (const float*)d_in[19];
    const float* lnfb = (const float*)d_in[20];
    float* out = (float*)d_out;

    float *x;
    f16 *qh, *ql, *k, *v;
    f16 *hh, *hl, *yh, *yl, *ffh, *ffl;
    f16 *wq, *wk, *wv, *wo, *w1, *w2;
    cudaGetSymbolAddress((void**)&x,   g_x);
    cudaGetSymbolAddress((void**)&qh,  g_qh);
    cudaGetSymbolAddress((void**)&ql,  g_ql);
    cudaGetSymbolAddress((void**)&k,   g_k);
    cudaGetSymbolAddress((void**)&v,   g_v);
    cudaGetSymbolAddress((void**)&hh,  g_hh);
    cudaGetSymbolAddress((void**)&hl,  g_hl);
    cudaGetSymbolAddress((void**)&yh,  g_yh);
    cudaGetSymbolAddress((void**)&yl,  g_yl);
    cudaGetSymbolAddress((void**)&ffh, g_ffh);
    cudaGetSymbolAddress((void**)&ffl, g_ffl);
    cudaGetSymbolAddress((void**)&wq,  g_wq);
    cudaGetSymbolAddress((void**)&wk,  g_wk);
    cudaGetSymbolAddress((void**)&wv,  g_wv);
    cudaGetSymbolAddress((void**)&wo,  g_wo);
    cudaGetSymbolAddress((void**)&w1,  g_w1);
    cudaGetSymbolAddress((void**)&w2,  g_w2);

    cudaFuncSetAttribute(attn_mma,
                         cudaFuncAttributeMaxDynamicSharedMemorySize, ATTN_SMEM);
    cudaFuncSetAttribute(qkv_mma,
                         cudaFuncAttributeMaxDynamicSharedMemorySize, GEMM_SMEM);
    cudaFuncSetAttribute(gemm_mma<0, true, 0>,
                         cudaFuncAttributeMaxDynamicSharedMemorySize, GEMM_SMEM);
    cudaFuncSetAttribute(gemm_mma<1, false, 1>,
                         cudaFuncAttributeMaxDynamicSharedMemorySize, GEMM_SMEM);

    const int ncc = NLAYER * CH * CH;
    const int ncf = NLAYER * CH * FFDIM;

    // launches 0-2: qkv weight converts (so launch 5 = qkv_mma for ncu)
    wcvt_kernel<<<ncc / 1024, 256>>>(Wq, wq, ncc);
    wcvt_kernel<<<ncc / 1024, 256>>>(Wk, wk, ncc);
    wcvt_kernel<<<ncc / 1024, 256>>>(Wv, wv, ncc);

    embed_kernel<<<(MROWS * CH) / 256, 256>>>(img, rad, pos);   // launch 3

    for (int l = 0; l < NLAYER; l++) {
        const size_t wcc = (size_t)l * CH * CH;
        const size_t wcf = (size_t)l * CH * FFDIM;

        ln_kernel<<<MROWS / 8, 256>>>(x, hh, hl, ln1w + l * CH, ln1b + l * CH);

        qkv_mma<<<dim3(12, MROWS / 128), 256, GEMM_SMEM>>>(   // launch 5 when l==0
            hh, hl, wq + wcc, wk + wcc, wv + wcc,
            bq + l * CH, bk + l * CH, bv + l * CH,
            qh, ql, k, v);

        if (l == 0) {
            wcvt_kernel<<<ncc / 1024, 256>>>(Wo, wo, ncc);
            wcvt_kernel<<<ncf / 1024, 256>>>(W1, w1, ncf);
            wcvt_kernel<<<ncf / 1024, 256>>>(W2, w2, ncf);
        }

        attn_mma<<<dim3(TOK / 128, NHEAD, BATCH), 256, ATTN_SMEM>>>(
            qh, ql, k, v, yh, yl);

        gemm_mma<0, true, 0><<<dim3(CH / 128, MROWS / 128), 256, GEMM_SMEM>>>(
            yh, yl, wo + wcc, bo + l * CH, x, x, nullptr, nullptr, CH, CH);

        ln_kernel<<<MROWS / 8, 256>>>(x, hh, hl, ln2w + l * CH, ln2b + l * CH);

        gemm_mma<1, false, 1><<<dim3(FFDIM / 128, MROWS / 128), 256, GEMM_SMEM>>>(
            hh, hl, w1 + wcf, b1 + l * FFDIM, nullptr,
            nullptr, ffh, ffl, FFDIM, CH);

        gemm_mma<0, true, 0><<<dim3(CH / 128, MROWS / 128), 256, GEMM_SMEM>>>(
            ffh, ffl, w2 + wcf, b2 + l * CH, x, x, nullptr, nullptr, CH, FFDIM);
    }

    lnf_kernel<<<MROWS / 8, 256>>>(x, out, lnfw, lnfb);
}

// round 15
// speedup vs baseline: 1.0284x; 1.0284x over previous
#include <cuda_runtime.h>
#include <cuda_fp16.h>
#include <cstdint>
#include <math.h>

// ---------------- problem constants ----------------
#define BATCH 16
#define TOK   1280
#define CH    512
#define NHEAD 8
#define HDIM  64
#define NLAYER 6
#define FFDIM 2048
#define MROWS (BATCH*TOK)    // 20480

typedef __half f16;

// ---------------- device scratch ----------------
__device__ float g_x [MROWS*CH];
__device__ f16  g_qh[MROWS*CH], g_ql[MROWS*CH];
__device__ f16  g_k [MROWS*CH];
__device__ f16  g_v [MROWS*CH];
__device__ f16  g_hh [MROWS*CH],   g_hl [MROWS*CH];
__device__ f16  g_yh [MROWS*CH],   g_yl [MROWS*CH];
__device__ f16  g_ffh[MROWS*FFDIM], g_ffl[MROWS*FFDIM];
// weights (single fp16)
__device__ f16 g_wq[NLAYER*CH*CH];
__device__ f16 g_wk[NLAYER*CH*CH];
__device__ f16 g_wv[NLAYER*CH*CH];
__device__ f16 g_wo[NLAYER*CH*CH];
__device__ f16 g_w1[NLAYER*CH*FFDIM];
__device__ f16 g_w2[NLAYER*FFDIM*CH];

// ---------------- helpers ----------------
__device__ __forceinline__ uint32_t smem_u32(const void* p) {
    uint32_t a;
    asm("{ .reg .u64 t; cvta.to.shared.u64 t, %1; cvt.u32.u64 %0, t; }"
        : "=r"(a) : "l"(p));
    return a;
}
// pack: low 16 = x0, high 16 = x1
__device__ __forceinline__ uint32_t pk_f16(float x0, float x1) {
    __half2 h = __floats2half2_rn(x0, x1);
    return *reinterpret_cast<uint32_t*>(&h);
}
__device__ __forceinline__ float f16_lo(uint32_t u) {
    __half2 h = *reinterpret_cast<__half2*>(&u);
    return __low2float(h);
}
__device__ __forceinline__ float f16_hi(uint32_t u) {
    __half2 h = *reinterpret_cast<__half2*>(&u);
    return __high2float(h);
}

__device__ __forceinline__ void cpasync16(uint32_t dst, const void* src) {
    asm volatile("cp.async.cg.shared.global [%0], [%1], 16;" :: "r"(dst), "l"(src));
}
__device__ __forceinline__ void cp_commit() {
    asm volatile("cp.async.commit_group;" ::: "memory");
}
__device__ __forceinline__ void cp_wait1() {
    asm volatile("cp.async.wait_group 1;" ::: "memory");
}
__device__ __forceinline__ void cp_wait0() {
    asm volatile("cp.async.wait_group 0;" ::: "memory");
}
__device__ __forceinline__ void ldsm4(uint32_t* r, uint32_t addr) {
    asm volatile("ldmatrix.sync.aligned.m8n8.x4.shared.b16 {%0,%1,%2,%3}, [%4];"
                 : "=r"(r[0]), "=r"(r[1]), "=r"(r[2]), "=r"(r[3]) : "r"(addr));
}
__device__ __forceinline__ void ldsm4t(uint32_t* r, uint32_t addr) {
    asm volatile("ldmatrix.sync.aligned.m8n8.x4.trans.shared.b16 {%0,%1,%2,%3}, [%4];"
                 : "=r"(r[0]), "=r"(r[1]), "=r"(r[2]), "=r"(r[3]) : "r"(addr));
}
__device__ __forceinline__ void mma16816(float* d, const uint32_t* a, const uint32_t* b) {
    asm volatile(
        "mma.sync.aligned.m16n8k16.row.col.f32.f16.f16.f32 "
        "{%0,%1,%2,%3}, {%4,%5,%6,%7}, {%8,%9}, {%0,%1,%2,%3};"
        : "+f"(d[0]), "+f"(d[1]), "+f"(d[2]), "+f"(d[3])
        : "r"(a[0]), "r"(a[1]), "r"(a[2]), "r"(a[3]), "r"(b[0]), "r"(b[1]));
}

// ---------------- weight convert: fp32 -> fp16 ----------------
__global__ void wcvt_kernel(const float* __restrict__ w,
                            f16* __restrict__ o, int n)
{
    int i = (blockIdx.x * blockDim.x + threadIdx.x) * 4;
    if (i >= n) return;
    float4 v = *(const float4*)(w + i);
    uint2 ho = {pk_f16(v.x, v.y), pk_f16(v.z, v.w)};
    *(uint2*)(o + i) = ho;
}

// ---------------- HMMA fp16 2-pass GEMM: 128x128 tile, 3-stage pipeline --------
// 8 warps 4(M)x2(N), warp tile 32x64, BK=32, one __syncthreads per chunk.
// D = (Ah + Al) @ Bh ; A split fp16 (22-bit), B single fp16.
#define APITCH 40
#define BPITCH 136
#define STG_A  10240          // 128*80 B
#define STG_B  8704           // 32*272 B
#define STG    (2*STG_A + STG_B)     // 29184 per stage (Ah, Al, Bh)
#define SOFF_AL STG_A
#define SOFF_BH (2*STG_A)
#define GEMM_SMEM (3*STG)     // 87552 B

// OUT: 0 = fp32 out (+RES optional), 1 = fp16 hi/lo split, 2 = fp16 single
template<int ACT, bool RES, int OUT>
__device__ __forceinline__ void gemm_body(
    const f16* __restrict__ Ahg, const f16* __restrict__ Alg,
    const f16* __restrict__ Bhg,
    const float* __restrict__ bias, const float* __restrict__ res,
    float* __restrict__ out, f16* __restrict__ outh, f16* __restrict__ outl,
    int N, int K, int m0, int n0)
{
    extern __shared__ char dynsm[];
    const uint32_t sb  = smem_u32(dynsm);

    const int tid  = threadIdx.x;
    const int lane = tid & 31, wid = tid >> 5;
    const int wm = wid >> 1, wn = wid & 1;

    const int lq = lane >> 3, lr = lane & 7;
    const uint32_t aOff = ((wm * 32 + (lq & 1) * 8 + lr) * APITCH + (lq >> 1) * 8) * 2;
    const uint32_t bOff = (((lq & 1) * 8 + lr) * BPITCH + wn * 64 + (lq >> 1) * 8) * 2;

    float acc[2][8][4];
#pragma unroll
    for (int i = 0; i < 2; i++)
#pragma unroll
        for (int j = 0; j < 8; j++)
#pragma unroll
            for (int c = 0; c < 4; c++) acc[i][j][c] = 0.f;

    const int nch = K >> 5;

    auto stage = [&](int ch, int st) {
        const int k0 = ch << 5;
        const uint32_t base = sb + st * STG;
#pragma unroll
        for (int i = 0; i < 2; i++) {
            int sid = tid + i * 256;
            int row = sid >> 2, sg = sid & 3;
            uint32_t d = base + row * 80 + sg * 16;
            size_t  g = (size_t)(m0 + row) * K + k0 + sg * 8;
            cpasync16(d,           Ahg + g);
            cpasync16(d + SOFF_AL, Alg + g);
        }
#pragma unroll
        for (int i = 0; i < 2; i++) {
            int sid = tid + i * 256;
            int row = sid >> 4, sg = sid & 15;
            uint32_t d = base + SOFF_BH + row * 272 + sg * 16;
            size_t  g = (size_t)(k0 + row) * N + n0 + sg * 8;
            cpasync16(d, Bhg + g);
        }
    };

    stage(0, 0);
    cp_commit();
    stage(1, 1);
    cp_commit();

    int st2 = 2;
    for (int ch = 0; ch < nch; ch++) {
        if (ch + 1 < nch) cp_wait1(); else cp_wait0();
        __syncthreads();
        if (ch + 2 < nch) {
            stage(ch + 2, st2);
            cp_commit();
            st2 = (st2 == 2) ? 0 : st2 + 1;
        }

        const uint32_t base = sb + (ch % 3) * STG;
        const uint32_t bAh = base, bAl = base + SOFF_AL;
        const uint32_t bBh = base + SOFF_BH;
#pragma unroll
        for (int s = 0; s < 2; s++) {
            uint32_t ah[2][4], al[2][4], b[8][2];
#pragma unroll
            for (int im = 0; im < 2; im++) {
                uint32_t d = (im * 16 * APITCH + s * 16) * 2;
                ldsm4(ah[im], bAh + aOff + d);
                ldsm4(al[im], bAl + aOff + d);
            }
#pragma unroll
            for (int jp = 0; jp < 4; jp++) {
                uint32_t tmp[4];
                ldsm4t(tmp, bBh + bOff + (s * 16 * BPITCH + jp * 16) * 2);
                b[2*jp][0] = tmp[0]; b[2*jp][1] = tmp[1];
                b[2*jp+1][0] = tmp[2]; b[2*jp+1][1] = tmp[3];
            }
#pragma unroll
            for (int im = 0; im < 2; im++)
#pragma unroll
                for (int jn = 0; jn < 8; jn++) mma16816(acc[im][jn], ah[im], b[jn]);
#pragma unroll
            for (int im = 0; im < 2; im++)
#pragma unroll
                for (int jn = 0; jn < 8; jn++) mma16816(acc[im][jn], al[im], b[jn]);
        }
    }

    const int gr = lane >> 2, gc = lane & 3;
#pragma unroll
    for (int im = 0; im < 2; im++) {
        int r0 = m0 + wm * 32 + im * 16 + gr;
#pragma unroll
        for (int jn = 0; jn < 8; jn++) {
            int c = n0 + wn * 64 + jn * 8 + gc * 2;
            float2 bv = *(const float2*)(bias + c);
            float v00 = acc[im][jn][0] + bv.x;
            float v01 = acc[im][jn][1] + bv.y;
            float v10 = acc[im][jn][2] + bv.x;
            float v11 = acc[im][jn][3] + bv.y;
            if (ACT == 1) {
                v00 = fmaxf(v00, 0.f); v01 = fmaxf(v01, 0.f);
                v10 = fmaxf(v10, 0.f); v11 = fmaxf(v11, 0.f);
            }
            if (RES) {
                float2 ra = *(const float2*)(res + (size_t)r0 * N + c);
                float2 rb = *(const float2*)(res + (size_t)(r0 + 8) * N + c);
                v00 += ra.x; v01 += ra.y; v10 += rb.x; v11 += rb.y;
            }
            if (OUT == 1) {
                uint32_t h0 = pk_f16(v00, v01);
                uint32_t h1 = pk_f16(v10, v11);
                uint32_t l0 = pk_f16(v00 - f16_lo(h0), v01 - f16_hi(h0));
                uint32_t l1 = pk_f16(v10 - f16_lo(h1), v11 - f16_hi(h1));
                *(uint32_t*)(outh + (size_t)r0 * N + c)       = h0;
                *(uint32_t*)(outh + (size_t)(r0 + 8) * N + c) = h1;
                *(uint32_t*)(outl + (size_t)r0 * N + c)       = l0;
                *(uint32_t*)(outl + (size_t)(r0 + 8) * N + c) = l1;
            } else if (OUT == 2) {
                *(uint32_t*)(outh + (size_t)r0 * N + c)       = pk_f16(v00, v01);
                *(uint32_t*)(outh + (size_t)(r0 + 8) * N + c) = pk_f16(v10, v11);
            } else {
                float2 o0 = {v00, v01}, o1 = {v10, v11};
                *(float2*)(out + (size_t)r0 * N + c)       = o0;
                *(float2*)(out + (size_t)(r0 + 8) * N + c) = o1;
            }
        }
    }
}

template<int ACT, bool RES, int OUT>
__global__ void __launch_bounds__(256, 2) gemm_mma(
    const f16* __restrict__ Ahg, const f16* __restrict__ Alg,
    const f16* __restrict__ Bhg,
    const float* __restrict__ bias, const float* __restrict__ res,
    float* __restrict__ out, f16* __restrict__ outh, f16* __restrict__ outl,
    int N, int K)
{
    gemm_body<ACT, RES, OUT>(Ahg, Alg, Bhg, bias, res, out, outh, outl,
                             N, K, blockIdx.y * 128, blockIdx.x * 128);
}

// fused QKV: blockIdx.x in [0,12): matrix = x>>2, n-tile = x&3
// q -> split hi/lo; k, v -> single fp16
__global__ void __launch_bounds__(256, 2) qkv_mma(
    const f16* __restrict__ Ahg, const f16* __restrict__ Alg,
    const f16* __restrict__ Bq, const f16* __restrict__ Bk, const f16* __restrict__ Bv,
    const float* __restrict__ c0, const float* __restrict__ c1,
    const float* __restrict__ c2,
    f16* __restrict__ oqh, f16* __restrict__ oql,
    f16* __restrict__ ok, f16* __restrict__ ov)
{
    int mat = blockIdx.x >> 2;
    int m0 = blockIdx.y * 128, n0 = (blockIdx.x & 3) * 128;
    if (mat == 0) {
        gemm_body<0, false, 1>(Ahg, Alg, Bq, c0, nullptr, nullptr, oqh, oql,
                               CH, CH, m0, n0);
    } else if (mat == 1) {
        gemm_body<0, false, 2>(Ahg, Alg, Bk, c1, nullptr, nullptr, ok, nullptr,
                               CH, CH, m0, n0);
    } else {
        gemm_body<0, false, 2>(Ahg, Alg, Bv, c2, nullptr, nullptr, ov, nullptr,
                               CH, CH, m0, n0);
    }
}

// ---------------- embed ----------------
__global__ void embed_kernel(const float* __restrict__ img,
                             const float* __restrict__ rad,
                             const float* __restrict__ pos)
{
    int idx = blockIdx.x * blockDim.x + threadIdx.x;
    int c   = idx & (CH - 1);
    int row = idx >> 9;
    int b   = row / TOK;
    int t   = row - b * TOK;
    float v;
    if (t < 1024) v = img[(size_t)(b * CH + c) * 1024 + t];
    else          v = rad[(size_t)(b * CH + c) * 256  + (t - 1024)];
    g_x[idx] = v + pos[t * CH + c];
}

// ---------------- layernorm -> fp16 hi/lo ----------------
__global__ void ln_kernel(const float* __restrict__ x,
                          f16* __restrict__ oh, f16* __restrict__ ol,
                          const float* __restrict__ w, const float* __restrict__ bb)
{
    int warp = threadIdx.x >> 5, lane = threadIdx.x & 31;
    int row  = blockIdx.x * 8 + warp;
    const float4* xr = (const float4*)(x + (size_t)row * CH);
    float4 v[4];
    float s = 0.f, s2 = 0.f;
#pragma unroll
    for (int i = 0; i < 4; i++) {
        v[i] = xr[lane + 32 * i];
        s  += v[i].x + v[i].y + v[i].z + v[i].w;
        s2 += v[i].x*v[i].x + v[i].y*v[i].y + v[i].z*v[i].z + v[i].w*v[i].w;
    }
#pragma unroll
    for (int off = 16; off; off >>= 1) {
        s  += __shfl_xor_sync(0xffffffffu, s,  off);
        s2 += __shfl_xor_sync(0xffffffffu, s2, off);
    }
    float m   = s * (1.f / CH);
    float inv = rsqrtf(s2 * (1.f / CH) - m * m + 1e-5f);
    const float4* wr = (const float4*)w;
    const float4* br = (const float4*)bb;
#pragma unroll
    for (int i = 0; i < 4; i++) {
        float4 wv = wr[lane + 32 * i], bv = br[lane + 32 * i];
        float o0 = (v[i].x - m) * inv * wv.x + bv.x;
        float o1 = (v[i].y - m) * inv * wv.y + bv.y;
        float o2 = (v[i].z - m) * inv * wv.z + bv.z;
        float o3 = (v[i].w - m) * inv * wv.w + bv.w;
        uint32_t h0 = pk_f16(o0, o1), h1 = pk_f16(o2, o3);
        uint32_t l0 = pk_f16(o0 - f16_lo(h0), o1 - f16_hi(h0));
        uint32_t l1 = pk_f16(o2 - f16_lo(h1), o3 - f16_hi(h1));
        size_t off = (size_t)row * CH + (lane + 32 * i) * 4;
        uint2 hh = {h0, h1}, ll = {l0, l1};
        *(uint2*)(oh + off) = hh;
        *(uint2*)(ol + off) = ll;
    }
}

// ---------------- final LN + scatter ----------------
__global__ void lnf_kernel(const float* __restrict__ x, float* __restrict__ out,
                           const float* __restrict__ w, const float* __restrict__ bb)
{
    int warp = threadIdx.x >> 5, lane = threadIdx.x & 31;
    int row  = blockIdx.x * 8 + warp;
    const float4* xr = (const float4*)(x + (size_t)row * CH);
    float4 v[4];
    float s = 0.f, s2 = 0.f;
#pragma unroll
    for (int i = 0; i < 4; i++) {
        v[i] = xr[lane + 32 * i];
        s  += v[i].x + v[i].y + v[i].z + v[i].w;
        s2 += v[i].x*v[i].x + v[i].y*v[i].y + v[i].z*v[i].z + v[i].w*v[i].w;
    }
#pragma unroll
    for (int off = 16; off; off >>= 1) {
        s  += __shfl_xor_sync(0xffffffffu, s,  off);
        s2 += __shfl_xor_sync(0xffffffffu, s2, off);
    }
    float m   = s * (1.f / CH);
    float inv = rsqrtf(s2 * (1.f / CH) - m * m + 1e-5f);
    int b = row / TOK, t = row - b * TOK;
    float* dst;
    if (t < 1024) dst = out + ((size_t)b * 1024 + t) * CH;
    else          dst = out + (size_t)BATCH*1024*CH + ((size_t)b*256 + (t-1024))*CH;
    const float4* wr = (const float4*)w;
    const float4* br = (const float4*)bb;
    float4* orow = (float4*)dst;
#pragma unroll
    for (int i = 0; i < 4; i++) {
        float4 wv = wr[lane + 32 * i], bv = br[lane + 32 * i], ov;
        ov.x = (v[i].x - m) * inv * wv.x + bv.x;
        ov.y = (v[i].y - m) * inv * wv.y + bv.y;
        ov.z = (v[i].z - m) * inv * wv.z + bv.z;
        ov.w = (v[i].w - m) * inv * wv.w + bv.w;
        orow[lane + 32 * i] = ov;
    }
}

// ---------------- MMA flash attention, fp16 2-pass ----------------
// CTA: 128 Q rows (8 warps x m16), KV tiles of 64 (double-buffered single-fp16).
// smem: Qh/Ql [128][72], K [2][64][72], V [2][64][72].
// NOTE: launch_bounds (256,2) — (256,3) caps regs at 84 and spills (R14 regression).
#define ATP 72
#define AT_QBYTES  18432
#define AT_KVB     9216
#define AT_OFF_KV  (2*AT_QBYTES)
#define ATTN_SMEM  (2*AT_QBYTES + 4*AT_KVB)   // 73728

__global__ void __launch_bounds__(256, 2) attn_mma(
    const f16* __restrict__ qh, const f16* __restrict__ ql,
    const f16* __restrict__ kg, const f16* __restrict__ vg,
    f16* __restrict__ yh, f16* __restrict__ yl)
{
    extern __shared__ char asm8[];
    const uint32_t sb = smem_u32(asm8);
    const int tid = threadIdx.x;
    const int lane = tid & 31, wid = tid >> 5;
    const int q0 = blockIdx.x * 128;
    const int h  = blockIdx.y;
    const int bz = blockIdx.z;
    const size_t gbase = (size_t)bz * TOK * CH + h * HDIM;

    // stage Q hi/lo (2048 slots / 256 thr = 8 iters)
#pragma unroll
    for (int i = 0; i < 8; i++) {
        int sid = tid + i * 256;
        int arr = sid >> 10;             // 0=hi, 1=lo
        int row = (sid >> 3) & 127;
        int sg  = sid & 7;
        const f16* src = (arr ? ql : qh) + gbase + (size_t)(q0 + row) * CH + sg * 8;
        cpasync16(sb + arr * AT_QBYTES + row * 144 + sg * 16, src);
    }

    auto stageKV = [&](int it, int bu) {
        const int k0 = it * 64;
#pragma unroll
        for (int i = 0; i < 4; i++) {
            int sid = tid + i * 256;
            int arr = sid >> 9;          // 0=K, 1=V
            int row = (sid >> 3) & 63;
            int sg  = sid & 7;
            const f16* base = arr ? vg : kg;
            cpasync16(sb + AT_OFF_KV + arr * (2 * AT_KVB) + bu * AT_KVB + row * 144 + sg * 16,
                      base + gbase + (size_t)(k0 + row) * CH + sg * 8);
        }
    };

    stageKV(0, 0);
    cp_commit();

    const int lq = lane >> 3, lr = lane & 7;
    const uint32_t aQ = ((wid * 16 + (lq & 1) * 8 + lr) * ATP + (lq >> 1) * 8) * 2;
    const uint32_t kRC = (((lq >> 1) * 8 + lr) * ATP + (lq & 1) * 8) * 2;
    const uint32_t vRC = (((lq & 1) * 8 + lr) * ATP + (lq >> 1) * 8) * 2;

    float of[8][4];
#pragma unroll
    for (int j = 0; j < 8; j++)
#pragma unroll
        for (int c = 0; c < 4; c++) of[j][c] = 0.f;
    float m0 = -1e30f, m1 = -1e30f, l0 = 0.f, l1 = 0.f;

    for (int it = 0; it < 20; it++) {
        const int bu = it & 1;
        if (it + 1 < 20) {
            stageKV(it + 1, bu ^ 1);
            cp_commit();
            cp_wait1();
        } else {
            cp_wait0();
        }
        __syncthreads();

        const uint32_t uK = sb + AT_OFF_KV + bu * AT_KVB;
        const uint32_t uV = sb + AT_OFF_KV + 2 * AT_KVB + bu * AT_KVB;

        // ---- S = Q K^T (2 passes: Qh, Ql vs K) ----
        float sf[8][4];
#pragma unroll
        for (int j = 0; j < 8; j++)
#pragma unroll
            for (int c = 0; c < 4; c++) sf[j][c] = 0.f;
#pragma unroll
        for (int s = 0; s < 4; s++) {
            uint32_t aH[4], aL[4];
            ldsm4(aH, sb + aQ + s * 32);
            ldsm4(aL, sb + AT_QBYTES + aQ + s * 32);
#pragma unroll
            for (int ng = 0; ng < 4; ng++) {
                uint32_t koff = kRC + (ng * 16 * ATP + s * 16) * 2;
                uint32_t kb[4];
                ldsm4(kb, uK + koff);
                mma16816(sf[2*ng],   aH, kb);
                mma16816(sf[2*ng+1], aH, kb + 2);
                mma16816(sf[2*ng],   aL, kb);
                mma16816(sf[2*ng+1], aL, kb + 2);
            }
        }

        // ---- online softmax on fragments ----
        float mloc0 = -1e30f, mloc1 = -1e30f;
#pragma unroll
        for (int j = 0; j < 8; j++) {
#pragma unroll
            for (int c = 0; c < 4; c++) sf[j][c] *= 0.125f;
            mloc0 = fmaxf(mloc0, fmaxf(sf[j][0], sf[j][1]));
            mloc1 = fmaxf(mloc1, fmaxf(sf[j][2], sf[j][3]));
        }
        mloc0 = fmaxf(mloc0, __shfl_xor_sync(0xffffffffu, mloc0, 1));
        mloc0 = fmaxf(mloc0, __shfl_xor_sync(0xffffffffu, mloc0, 2));
        mloc1 = fmaxf(mloc1, __shfl_xor_sync(0xffffffffu, mloc1, 1));
        mloc1 = fmaxf(mloc1, __shfl_xor_sync(0xffffffffu, mloc1, 2));
        float mn0 = fmaxf(m0, mloc0), mn1 = fmaxf(m1, mloc1);
        float al0 = __expf(m0 - mn0), al1 = __expf(m1 - mn1);
        m0 = mn0; m1 = mn1;

        uint32_t php[8], php2[8], plp[8], plp2[8];
        float sum0 = 0.f, sum1 = 0.f;
#pragma unroll
        for (int j = 0; j < 8; j++) {
            float p0 = __expf(sf[j][0] - m0);
            float p1 = __expf(sf[j][1] - m0);
            float p2 = __expf(sf[j][2] - m1);
            float p3 = __expf(sf[j][3] - m1);
            sum0 += p0 + p1; sum1 += p2 + p3;
            uint32_t h0 = pk_f16(p0, p1), h1 = pk_f16(p2, p3);
            php[j]  = h0;  php2[j] = h1;
            plp[j]  = pk_f16(p0 - f16_lo(h0), p1 - f16_hi(h0));
            plp2[j] = pk_f16(p2 - f16_lo(h1), p3 - f16_hi(h1));
        }
        sum0 += __shfl_xor_sync(0xffffffffu, sum0, 1);
        sum0 += __shfl_xor_sync(0xffffffffu, sum0, 2);
        sum1 += __shfl_xor_sync(0xffffffffu, sum1, 1);
        sum1 += __shfl_xor_sync(0xffffffffu, sum1, 2);
        l0 = l0 * al0 + sum0;
        l1 = l1 * al1 + sum1;
#pragma unroll
        for (int j = 0; j < 8; j++) {
            of[j][0] *= al0; of[j][1] *= al0;
            of[j][2] *= al1; of[j][3] *= al1;
        }

        // ---- O += P V (2 passes: Ph, Pl vs V) ----
#pragma unroll
        for (int t = 0; t < 4; t++) {
            uint32_t aPh[4] = {php[2*t], php2[2*t], php[2*t+1], php2[2*t+1]};
            uint32_t aPl[4] = {plp[2*t], plp2[2*t], plp[2*t+1], plp2[2*t+1]};
#pragma unroll
            for (int jp = 0; jp < 4; jp++) {
                uint32_t voff = vRC + (t * 16 * ATP + jp * 16) * 2;
                uint32_t vb[4];
                ldsm4t(vb, uV + voff);
                mma16816(of[2*jp],   aPh, vb);
                mma16816(of[2*jp+1], aPh, vb + 2);
                mma16816(of[2*jp],   aPl, vb);
                mma16816(of[2*jp+1], aPl, vb + 2);
            }
        }
        __syncthreads();
    }

    // ---- epilogue: O /= l, write y fp16 hi/lo ----
    const int gr = lane >> 2, gc = lane & 3;
    const float inv0 = 1.f / l0, inv1 = 1.f / l1;
    const size_t rA = gbase + (size_t)(q0 + wid * 16 + gr) * CH;
    const size_t rB = rA + (size_t)8 * CH;
#pragma unroll
    for (int j = 0; j < 8; j++) {
        float o0 = of[j][0] * inv0, o1 = of[j][1] * inv0;
        float o2 = of[j][2] * inv1, o3 = of[j][3] * inv1;
        uint32_t h0 = pk_f16(o0, o1), h1 = pk_f16(o2, o3);
        uint32_t lo0 = pk_f16(o0 - f16_lo(h0), o1 - f16_hi(h0));
        uint32_t lo1 = pk_f16(o2 - f16_lo(h1), o3 - f16_hi(h1));
        int c = j * 8 + gc * 2;
        *(uint32_t*)(yh + rA + c) = h0;
        *(uint32_t*)(yl + rA + c) = lo0;
        *(uint32_t*)(yh + rB + c) = h1;
        *(uint32_t*)(yl + rB + c) = lo1;
    }
}

// ---------------- orchestration ----------------
extern "C" void kernel_launch(void* const* d_in, const int* in_sizes, int n_in,
                              void* d_out, int out_size)
{
    const float* img  = (const float*)d_in[0];
    const float* rad  = (const float*)d_in[1];
    const float* pos  = (const float*)d_in[2];
    const float* ln1w = (const float*)d_in[3];
    const float* ln1b = (const float*)d_in[4];
    const float* Wq   = (const float*)d_in[5];
    const float* bq   = (const float*)d_in[6];
    const float* Wk   = (const float*)d_in[7];
    const float* bk   = (const float*)d_in[8];
    const float* Wv   = (const float*)d_in[9];
    const float* bv   = (const float*)d_in[10];
    const float* Wo   = (const float*)d_in[11];
    const float* bo   = (const float*)d_in[12];
    const float* ln2w = (const float*)d_in[13];
    const float* ln2b = (const float*)d_in[14];
    const float* W1   = (const float*)d_in[15];
    const float* b1   = (const float*)d_in[16];
    const float* W2   = (const float*)d_in[17];
    const float* b2   = (const float*)d_in[18];
    const float* lnfw = (const float*)d_in[19];
    const float* lnfb = (const float*)d_in[20];
    float* out = (float*)d_out;

    float *x;
    f16 *qh, *ql, *k, *v;
    f16 *hh, *hl, *yh, *yl, *ffh, *ffl;
    f16 *wq, *wk, *wv, *wo, *w1, *w2;
    cudaGetSymbolAddress((void**)&x,   g_x);
    cudaGetSymbolAddress((void**)&qh,  g_qh);
    cudaGetSymbolAddress((void**)&ql,  g_ql);
    cudaGetSymbolAddress((void**)&k,   g_k);
    cudaGetSymbolAddress((void**)&v,   g_v);
    cudaGetSymbolAddress((void**)&hh,  g_hh);
    cudaGetSymbolAddress((void**)&hl,  g_hl);
    cudaGetSymbolAddress((void**)&yh,  g_yh);
    cudaGetSymbolAddress((void**)&yl,  g_yl);
    cudaGetSymbolAddress((void**)&ffh, g_ffh);
    cudaGetSymbolAddress((void**)&ffl, g_ffl);
    cudaGetSymbolAddress((void**)&wq,  g_wq);
    cudaGetSymbolAddress((void**)&wk,  g_wk);
    cudaGetSymbolAddress((void**)&wv,  g_wv);
    cudaGetSymbolAddress((void**)&wo,  g_wo);
    cudaGetSymbolAddress((void**)&w1,  g_w1);
    cudaGetSymbolAddress((void**)&w2,  g_w2);

    cudaFuncSetAttribute(attn_mma,
                         cudaFuncAttributeMaxDynamicSharedMemorySize, ATTN_SMEM);
    cudaFuncSetAttribute(qkv_mma,
                         cudaFuncAttributeMaxDynamicSharedMemorySize, GEMM_SMEM);
    cudaFuncSetAttribute(gemm_mma<0, true, 0>,
                         cudaFuncAttributeMaxDynamicSharedMemorySize, GEMM_SMEM);
    cudaFuncSetAttribute(gemm_mma<1, false, 1>,
                         cudaFuncAttributeMaxDynamicSharedMemorySize, GEMM_SMEM);

    const int ncc = NLAYER * CH * CH;
    const int ncf = NLAYER * CH * FFDIM;

    wcvt_kernel<<<ncc / 1024, 256>>>(Wq, wq, ncc);
    wcvt_kernel<<<ncc / 1024, 256>>>(Wk, wk, ncc);
    wcvt_kernel<<<ncc / 1024, 256>>>(Wv, wv, ncc);

    embed_kernel<<<(MROWS * CH) / 256, 256>>>(img, rad, pos);

    for (int l = 0; l < NLAYER; l++) {
        const size_t wcc = (size_t)l * CH * CH;
        const size_t wcf = (size_t)l * CH * FFDIM;

        ln_kernel<<<MROWS / 8, 256>>>(x, hh, hl, ln1w + l * CH, ln1b + l * CH);

        qkv_mma<<<dim3(12, MROWS / 128), 256, GEMM_SMEM>>>(
            hh, hl, wq + wcc, wk + wcc, wv + wcc,
            bq + l * CH, bk + l * CH, bv + l * CH,
            qh, ql, k, v);

        if (l == 0) {
            wcvt_kernel<<<ncc / 1024, 256>>>(Wo, wo, ncc);
            wcvt_kernel<<<ncf / 1024, 256>>>(W1, w1, ncf);
            wcvt_kernel<<<ncf / 1024, 256>>>(W2, w2, ncf);
        }

        attn_mma<<<dim3(TOK / 128, NHEAD, BATCH), 256, ATTN_SMEM>>>(
            qh, ql, k, v, yh, yl);

        gemm_mma<0, true, 0><<<dim3(CH / 128, MROWS / 128), 256, GEMM_SMEM>>>(
            yh, yl, wo + wcc, bo + l * CH, x, x, nullptr, nullptr, CH, CH);

        ln_kernel<<<MROWS / 8, 256>>>(x, hh, hl, ln2w + l * CH, ln2b + l * CH);

        gemm_mma<1, false, 1><<<dim3(FFDIM / 128, MROWS / 128), 256, GEMM_SMEM>>>(
            hh, hl, w1 + wcf, b1 + l * FFDIM, nullptr,
            nullptr, ffh, ffl, FFDIM, CH);

        gemm_mma<0, true, 0><<<dim3(CH / 128, MROWS / 128), 256, GEMM_SMEM>>>(
            ffh, ffl, w2 + wcf, b2 + l * CH, x, x, nullptr, nullptr, CH, FFDIM);
    }

    lnf_kernel<<<MROWS / 8, 256>>>(x, out, lnfw, lnfb);
}

// round 16
// speedup vs baseline: 1.1625x; 1.1304x over previous
#include <cuda_runtime.h>
#include <cuda_bf16.h>
#include <cstdint>
#include <math.h>

// ---------------- problem constants ----------------
#define BATCH 16
#define TOK   1280
#define CH    512
#define NHEAD 8
#define HDIM  64
#define NLAYER 6
#define FFDIM 2048
#define MROWS (BATCH*TOK)    // 20480

typedef __nv_bfloat16 bf16;

// ---------------- device scratch ----------------
__device__ float g_x [MROWS*CH];
__device__ bf16  g_qh[MROWS*CH], g_ql[MROWS*CH];
__device__ bf16  g_kh[MROWS*CH], g_kl[MROWS*CH];
__device__ bf16  g_vh[MROWS*CH], g_vl[MROWS*CH];
__device__ bf16  g_hh [MROWS*CH],   g_hl [MROWS*CH];
__device__ bf16  g_yh [MROWS*CH],   g_yl [MROWS*CH];
__device__ bf16  g_ffh[MROWS*FFDIM], g_ffl[MROWS*FFDIM];
// weight splits
__device__ bf16 g_wqh[NLAYER*CH*CH],  g_wql[NLAYER*CH*CH];
__device__ bf16 g_wkh[NLAYER*CH*CH],  g_wkl[NLAYER*CH*CH];
__device__ bf16 g_wvh[NLAYER*CH*CH],  g_wvl[NLAYER*CH*CH];
__device__ bf16 g_woh[NLAYER*CH*CH],  g_wol[NLAYER*CH*CH];
__device__ bf16 g_w1h[NLAYER*CH*FFDIM], g_w1l[NLAYER*CH*FFDIM];
__device__ bf16 g_w2h[NLAYER*FFDIM*CH], g_w2l[NLAYER*FFDIM*CH];

// ---------------- helpers ----------------
__device__ __forceinline__ uint32_t smem_u32(const void* p) {
    uint32_t a;
    asm("{ .reg .u64 t; cvta.to.shared.u64 t, %1; cvt.u32.u64 %0, t; }"
        : "=r"(a) : "l"(p));
    return a;
}
__device__ __forceinline__ uint32_t pk_bf16(float x0, float x1) {
    uint32_t r;
    asm("cvt.rn.bf16x2.f32 %0, %1, %2;" : "=r"(r) : "f"(x1), "f"(x0));
    return r;
}
__device__ __forceinline__ float bf_lo(uint32_t u) { return __uint_as_float(u << 16); }
__device__ __forceinline__ float bf_hi(uint32_t u) { return __uint_as_float(u & 0xFFFF0000u); }

__device__ __forceinline__ void cpasync16(uint32_t dst, const void* src) {
    asm volatile("cp.async.cg.shared.global [%0], [%1], 16;" :: "r"(dst), "l"(src));
}
__device__ __forceinline__ void cp_commit() {
    asm volatile("cp.async.commit_group;" ::: "memory");
}
__device__ __forceinline__ void cp_wait1() {
    asm volatile("cp.async.wait_group 1;" ::: "memory");
}
__device__ __forceinline__ void cp_wait0() {
    asm volatile("cp.async.wait_group 0;" ::: "memory");
}
__device__ __forceinline__ void ldsm4(uint32_t* r, uint32_t addr) {
    asm volatile("ldmatrix.sync.aligned.m8n8.x4.shared.b16 {%0,%1,%2,%3}, [%4];"
                 : "=r"(r[0]), "=r"(r[1]), "=r"(r[2]), "=r"(r[3]) : "r"(addr));
}
__device__ __forceinline__ void ldsm4t(uint32_t* r, uint32_t addr) {
    asm volatile("ldmatrix.sync.aligned.m8n8.x4.trans.shared.b16 {%0,%1,%2,%3}, [%4];"
                 : "=r"(r[0]), "=r"(r[1]), "=r"(r[2]), "=r"(r[3]) : "r"(addr));
}
__device__ __forceinline__ void mma16816(float* d, const uint32_t* a, const uint32_t* b) {
    asm volatile(
        "mma.sync.aligned.m16n8k16.row.col.f32.bf16.bf16.f32 "
        "{%0,%1,%2,%3}, {%4,%5,%6,%7}, {%8,%9}, {%0,%1,%2,%3};"
        : "+f"(d[0]), "+f"(d[1]), "+f"(d[2]), "+f"(d[3])
        : "r"(a[0]), "r"(a[1]), "r"(a[2]), "r"(a[3]), "r"(b[0]), "r"(b[1]));
}

// ---------------- merged weight split: all 6 matrices in ONE launch ----------------
__global__ void wsplit_all(
    const float* __restrict__ Wq, const float* __restrict__ Wk,
    const float* __restrict__ Wv, const float* __restrict__ Wo,
    const float* __restrict__ W1, const float* __restrict__ W2,
    bf16* __restrict__ wqh, bf16* __restrict__ wql,
    bf16* __restrict__ wkh, bf16* __restrict__ wkl,
    bf16* __restrict__ wvh, bf16* __restrict__ wvl,
    bf16* __restrict__ woh, bf16* __restrict__ wol,
    bf16* __restrict__ w1h, bf16* __restrict__ w1l,
    bf16* __restrict__ w2h, bf16* __restrict__ w2l)
{
    const int ncc = NLAYER * CH * CH;
    const int ncf = NLAYER * CH * FFDIM;
    int mat = blockIdx.y;
    const float* w; bf16 *hi, *lo; int n;
    switch (mat) {
        case 0: w = Wq; hi = wqh; lo = wql; n = ncc; break;
        case 1: w = Wk; hi = wkh; lo = wkl; n = ncc; break;
        case 2: w = Wv; hi = wvh; lo = wvl; n = ncc; break;
        case 3: w = Wo; hi = woh; lo = wol; n = ncc; break;
        case 4: w = W1; hi = w1h; lo = w1l; n = ncf; break;
        default: w = W2; hi = w2h; lo = w2l; n = ncf; break;
    }
    int i = (blockIdx.x * blockDim.x + threadIdx.x) * 4;
    if (i >= n) return;
    float4 v = *(const float4*)(w + i);
    uint32_t h0 = pk_bf16(v.x, v.y);
    uint32_t h1 = pk_bf16(v.z, v.w);
    uint32_t l0 = pk_bf16(v.x - bf_lo(h0), v.y - bf_hi(h0));
    uint32_t l1 = pk_bf16(v.z - bf_lo(h1), v.w - bf_hi(h1));
    uint2 ho = {h0, h1}, loo = {l0, l1};
    *(uint2*)(hi + i) = ho;
    *(uint2*)(lo + i) = loo;
}

// ---------------- HMMA bf16x3 GEMM: 128x128 tile, 3-stage pipeline ----------------
#define APITCH 40
#define BPITCH 136
#define STG_A  10240
#define STG_B  8704
#define STG    (2*STG_A + 2*STG_B)   // 37888 per stage
#define SOFF_AL STG_A
#define SOFF_BH (2*STG_A)
#define SOFF_BL (2*STG_A + STG_B)
#define GEMM_SMEM (3*STG)     // 113664 B

template<int ACT, bool RES, bool OSPLIT>
__device__ __forceinline__ void gemm_body(
    const bf16* __restrict__ Ahg, const bf16* __restrict__ Alg,
    const bf16* __restrict__ Bhg, const bf16* __restrict__ Blg,
    const float* __restrict__ bias, const float* __restrict__ res,
    float* __restrict__ out, bf16* __restrict__ outh, bf16* __restrict__ outl,
    int N, int K, int m0, int n0)
{
    extern __shared__ char dynsm[];
    const uint32_t sb  = smem_u32(dynsm);

    const int tid  = threadIdx.x;
    const int lane = tid & 31, wid = tid >> 5;
    const int wm = wid >> 1, wn = wid & 1;

    const int lq = lane >> 3, lr = lane & 7;
    const uint32_t aOff = ((wm * 32 + (lq & 1) * 8 + lr) * APITCH + (lq >> 1) * 8) * 2;
    const uint32_t bOff = (((lq & 1) * 8 + lr) * BPITCH + wn * 64 + (lq >> 1) * 8) * 2;

    float acc[2][8][4];
#pragma unroll
    for (int i = 0; i < 2; i++)
#pragma unroll
        for (int j = 0; j < 8; j++)
#pragma unroll
            for (int c = 0; c < 4; c++) acc[i][j][c] = 0.f;

    const int nch = K >> 5;

    auto stage = [&](int ch, int st) {
        const int k0 = ch << 5;
        const uint32_t base = sb + st * STG;
#pragma unroll
        for (int i = 0; i < 2; i++) {
            int sid = tid + i * 256;
            int row = sid >> 2, sg = sid & 3;
            uint32_t d = base + row * 80 + sg * 16;
            size_t  g = (size_t)(m0 + row) * K + k0 + sg * 8;
            cpasync16(d,           Ahg + g);
            cpasync16(d + SOFF_AL, Alg + g);
        }
#pragma unroll
        for (int i = 0; i < 2; i++) {
            int sid = tid + i * 256;
            int row = sid >> 4, sg = sid & 15;
            uint32_t d = base + SOFF_BH + row * 272 + sg * 16;
            size_t  g = (size_t)(k0 + row) * N + n0 + sg * 8;
            cpasync16(d,         Bhg + g);
            cpasync16(d + STG_B, Blg + g);
        }
    };

    stage(0, 0);
    cp_commit();
    stage(1, 1);
    cp_commit();

    int st2 = 2;
    for (int ch = 0; ch < nch; ch++) {
        if (ch + 1 < nch) cp_wait1(); else cp_wait0();
        __syncthreads();
        if (ch + 2 < nch) {
            stage(ch + 2, st2);
            cp_commit();
            st2 = (st2 == 2) ? 0 : st2 + 1;
        }

        const uint32_t base = sb + (ch % 3) * STG;
        const uint32_t bAh = base, bAl = base + SOFF_AL;
        const uint32_t bBh = base + SOFF_BH, bBl = base + SOFF_BL;
#pragma unroll
        for (int s = 0; s < 2; s++) {
            uint32_t ah[2][4], al[2][4], b[8][2];
#pragma unroll
            for (int im = 0; im < 2; im++) {
                uint32_t d = (im * 16 * APITCH + s * 16) * 2;
                ldsm4(ah[im], bAh + aOff + d);
                ldsm4(al[im], bAl + aOff + d);
            }
#pragma unroll
            for (int jp = 0; jp < 4; jp++) {
                uint32_t tmp[4];
                ldsm4t(tmp, bBh + bOff + (s * 16 * BPITCH + jp * 16) * 2);
                b[2*jp][0] = tmp[0]; b[2*jp][1] = tmp[1];
                b[2*jp+1][0] = tmp[2]; b[2*jp+1][1] = tmp[3];
            }
#pragma unroll
            for (int im = 0; im < 2; im++)
#pragma unroll
                for (int jn = 0; jn < 8; jn++) mma16816(acc[im][jn], ah[im], b[jn]);
#pragma unroll
            for (int im = 0; im < 2; im++)
#pragma unroll
                for (int jn = 0; jn < 8; jn++) mma16816(acc[im][jn], al[im], b[jn]);
#pragma unroll
            for (int jp = 0; jp < 4; jp++) {
                uint32_t tmp[4];
                ldsm4t(tmp, bBl + bOff + (s * 16 * BPITCH + jp * 16) * 2);
                b[2*jp][0] = tmp[0]; b[2*jp][1] = tmp[1];
                b[2*jp+1][0] = tmp[2]; b[2*jp+1][1] = tmp[3];
            }
#pragma unroll
            for (int im = 0; im < 2; im++)
#pragma unroll
                for (int jn = 0; jn < 8; jn++) mma16816(acc[im][jn], ah[im], b[jn]);
        }
    }

    const int gr = lane >> 2, gc = lane & 3;
#pragma unroll
    for (int im = 0; im < 2; im++) {
        int r0 = m0 + wm * 32 + im * 16 + gr;
#pragma unroll
        for (int jn = 0; jn < 8; jn++) {
            int c = n0 + wn * 64 + jn * 8 + gc * 2;
            float2 bv = *(const float2*)(bias + c);
            float v00 = acc[im][jn][0] + bv.x;
            float v01 = acc[im][jn][1] + bv.y;
            float v10 = acc[im][jn][2] + bv.x;
            float v11 = acc[im][jn][3] + bv.y;
            if (ACT == 1) {
                v00 = fmaxf(v00, 0.f); v01 = fmaxf(v01, 0.f);
                v10 = fmaxf(v10, 0.f); v11 = fmaxf(v11, 0.f);
            }
            if (RES) {
                float2 ra = *(const float2*)(res + (size_t)r0 * N + c);
                float2 rb = *(const float2*)(res + (size_t)(r0 + 8) * N + c);
                v00 += ra.x; v01 += ra.y; v10 += rb.x; v11 += rb.y;
            }
            if (OSPLIT) {
                uint32_t h0 = pk_bf16(v00, v01);
                uint32_t h1 = pk_bf16(v10, v11);
                uint32_t l0 = pk_bf16(v00 - bf_lo(h0), v01 - bf_hi(h0));
                uint32_t l1 = pk_bf16(v10 - bf_lo(h1), v11 - bf_hi(h1));
                *(uint32_t*)(outh + (size_t)r0 * N + c)       = h0;
                *(uint32_t*)(outh + (size_t)(r0 + 8) * N + c) = h1;
                *(uint32_t*)(outl + (size_t)r0 * N + c)       = l0;
                *(uint32_t*)(outl + (size_t)(r0 + 8) * N + c) = l1;
            } else {
                float2 o0 = {v00, v01}, o1 = {v10, v11};
                *(float2*)(out + (size_t)r0 * N + c)       = o0;
                *(float2*)(out + (size_t)(r0 + 8) * N + c) = o1;
            }
        }
    }
}

template<int ACT, bool RES, bool OSPLIT>
__global__ void __launch_bounds__(256, 2) gemm_mma(
    const bf16* __restrict__ Ahg, const bf16* __restrict__ Alg,
    const bf16* __restrict__ Bhg, const bf16* __restrict__ Blg,
    const float* __restrict__ bias, const float* __restrict__ res,
    float* __restrict__ out, bf16* __restrict__ outh, bf16* __restrict__ outl,
    int N, int K)
{
    gemm_body<ACT, RES, OSPLIT>(Ahg, Alg, Bhg, Blg, bias, res, out, outh, outl,
                                N, K, blockIdx.y * 128, blockIdx.x * 128);
}

// fused QKV with split bf16 outputs: blockIdx.x in [0,12)
__global__ void __launch_bounds__(256, 2) qkv_mma(
    const bf16* __restrict__ Ahg, const bf16* __restrict__ Alg,
    const bf16* __restrict__ B0h, const bf16* __restrict__ B0l,
    const bf16* __restrict__ B1h, const bf16* __restrict__ B1l,
    const bf16* __restrict__ B2h, const bf16* __restrict__ B2l,
    const float* __restrict__ c0, const float* __restrict__ c1,
    const float* __restrict__ c2,
    bf16* __restrict__ o0h, bf16* __restrict__ o0l,
    bf16* __restrict__ o1h, bf16* __restrict__ o1l,
    bf16* __restrict__ o2h, bf16* __restrict__ o2l)
{
    int mat = blockIdx.x >> 2;
    const bf16* Bh    = (mat == 0) ? B0h : (mat == 1) ? B1h : B2h;
    const bf16* Bl    = (mat == 0) ? B0l : (mat == 1) ? B1l : B2l;
    const float* bias = (mat == 0) ? c0 : (mat == 1) ? c1 : c2;
    bf16* oh          = (mat == 0) ? o0h : (mat == 1) ? o1h : o2h;
    bf16* ol          = (mat == 0) ? o0l : (mat == 1) ? o1l : o2l;
    gemm_body<0, false, true>(Ahg, Alg, Bh, Bl, bias, nullptr, nullptr, oh, ol,
                              CH, CH, blockIdx.y * 128, (blockIdx.x & 3) * 128);
}

// ---------------- coalesced embed: smem 32x32 transpose ----------------
// grid (TOK/32, CH/32, BATCH), block 256 (32x8)
__global__ void embed_kernel(const float* __restrict__ img,
                             const float* __restrict__ rad,
                             const float* __restrict__ pos)
{
    __shared__ float tile[32][33];
    const int b  = blockIdx.z;
    const int t0 = blockIdx.x * 32, c0 = blockIdx.y * 32;
    const int tx = threadIdx.x & 31, ty = threadIdx.x >> 5;
    const int tt = t0 + tx;
#pragma unroll
    for (int i = 0; i < 4; i++) {
        int c = c0 + ty + i * 8;
        float v;
        if (t0 < 1024) v = img[(size_t)(b * CH + c) * 1024 + tt];
        else           v = rad[(size_t)(b * CH + c) * 256  + (tt - 1024)];
        tile[ty + i * 8][tx] = v;
    }
    __syncthreads();
#pragma unroll
    for (int i = 0; i < 4; i++) {
        int tl = ty + i * 8;
        int t  = t0 + tl;
        g_x[((size_t)b * TOK + t) * CH + c0 + tx] =
            tile[tx][tl] + pos[t * CH + c0 + tx];
    }
}

// ---------------- layernorm -> bf16 hi/lo ----------------
__global__ void ln_kernel(const float* __restrict__ x,
                          bf16* __restrict__ oh, bf16* __restrict__ ol,
                          const float* __restrict__ w, const float* __restrict__ bb)
{
    int warp = threadIdx.x >> 5, lane = threadIdx.x & 31;
    int row  = blockIdx.x * 8 + warp;
    const float4* xr = (const float4*)(x + (size_t)row * CH);
    float4 v[4];
    float s = 0.f, s2 = 0.f;
#pragma unroll
    for (int i = 0; i < 4; i++) {
        v[i] = xr[lane + 32 * i];
        s  += v[i].x + v[i].y + v[i].z + v[i].w;
        s2 += v[i].x*v[i].x + v[i].y*v[i].y + v[i].z*v[i].z + v[i].w*v[i].w;
    }
#pragma unroll
    for (int off = 16; off; off >>= 1) {
        s  += __shfl_xor_sync(0xffffffffu, s,  off);
        s2 += __shfl_xor_sync(0xffffffffu, s2, off);
    }
    float m   = s * (1.f / CH);
    float inv = rsqrtf(s2 * (1.f / CH) - m * m + 1e-5f);
    const float4* wr = (const float4*)w;
    const float4* br = (const float4*)bb;
#pragma unroll
    for (int i = 0; i < 4; i++) {
        float4 wv = wr[lane + 32 * i], bv = br[lane + 32 * i];
        float o0 = (v[i].x - m) * inv * wv.x + bv.x;
        float o1 = (v[i].y - m) * inv * wv.y + bv.y;
        float o2 = (v[i].z - m) * inv * wv.z + bv.z;
        float o3 = (v[i].w - m) * inv * wv.w + bv.w;
        uint32_t h0 = pk_bf16(o0, o1), h1 = pk_bf16(o2, o3);
        uint32_t l0 = pk_bf16(o0 - bf_lo(h0), o1 - bf_hi(h0));
        uint32_t l1 = pk_bf16(o2 - bf_lo(h1), o3 - bf_hi(h1));
        size_t off = (size_t)row * CH + (lane + 32 * i) * 4;
        uint2 hh = {h0, h1}, ll = {l0, l1};
        *(uint2*)(oh + off) = hh;
        *(uint2*)(ol + off) = ll;
    }
}

// ---------------- final LN + scatter ----------------
__global__ void lnf_kernel(const float* __restrict__ x, float* __restrict__ out,
                           const float* __restrict__ w, const float* __restrict__ bb)
{
    int warp = threadIdx.x >> 5, lane = threadIdx.x & 31;
    int row  = blockIdx.x * 8 + warp;
    const float4* xr = (const float4*)(x + (size_t)row * CH);
    float4 v[4];
    float s = 0.f, s2 = 0.f;
#pragma unroll
    for (int i = 0; i < 4; i++) {
        v[i] = xr[lane + 32 * i];
        s  += v[i].x + v[i].y + v[i].z + v[i].w;
        s2 += v[i].x*v[i].x + v[i].y*v[i].y + v[i].z*v[i].z + v[i].w*v[i].w;
    }
#pragma unroll
    for (int off = 16; off; off >>= 1) {
        s  += __shfl_xor_sync(0xffffffffu, s,  off);
        s2 += __shfl_xor_sync(0xffffffffu, s2, off);
    }
    float m   = s * (1.f / CH);
    float inv = rsqrtf(s2 * (1.f / CH) - m * m + 1e-5f);
    int b = row / TOK, t = row - b * TOK;
    float* dst;
    if (t < 1024) dst = out + ((size_t)b * 1024 + t) * CH;
    else          dst = out + (size_t)BATCH*1024*CH + ((size_t)b*256 + (t-1024))*CH;
    const float4* wr = (const float4*)w;
    const float4* br = (const float4*)bb;
    float4* orow = (float4*)dst;
#pragma unroll
    for (int i = 0; i < 4; i++) {
        float4 wv = wr[lane + 32 * i], bv = br[lane + 32 * i], ov;
        ov.x = (v[i].x - m) * inv * wv.x + bv.x;
        ov.y = (v[i].y - m) * inv * wv.y + bv.y;
        ov.z = (v[i].z - m) * inv * wv.z + bv.z;
        ov.w = (v[i].w - m) * inv * wv.w + bv.w;
        orow[lane + 32 * i] = ov;
    }
}

// ---------------- MMA flash attention (R8/R13 proven) ----------------
#define ATP 72
#define AT_QBYTES  18432
#define AT_KVB     9216
#define AT_OFF_KV  (2*AT_QBYTES)
#define ATTN_SMEM  (2*AT_QBYTES + 8*AT_KVB)   // 110592

__global__ void __launch_bounds__(256, 2) attn_mma(
    const bf16* __restrict__ qh, const bf16* __restrict__ ql,
    const bf16* __restrict__ kh, const bf16* __restrict__ kl,
    const bf16* __restrict__ vh, const bf16* __restrict__ vl,
    bf16* __restrict__ yh, bf16* __restrict__ yl)
{
    extern __shared__ char asm8[];
    const uint32_t sb = smem_u32(asm8);
    const int tid = threadIdx.x;
    const int lane = tid & 31, wid = tid >> 5;
    const int q0 = blockIdx.x * 128;
    const int h  = blockIdx.y;
    const int bz = blockIdx.z;
    const size_t gbase = (size_t)bz * TOK * CH + h * HDIM;

#pragma unroll
    for (int i = 0; i < 8; i++) {
        int sid = tid + i * 256;
        int arr = sid >> 10;
        int row = (sid >> 3) & 127;
        int sg  = sid & 7;
        const bf16* src = (arr ? ql : qh) + gbase + (size_t)(q0 + row) * CH + sg * 8;
        cpasync16(sb + arr * AT_QBYTES + row * 144 + sg * 16, src);
    }

    auto stageKV = [&](int it, int bu) {
        const int k0 = it * 64;
#pragma unroll
        for (int i = 0; i < 8; i++) {
            int sid = tid + i * 256;
            int arr = sid >> 9;
            int row = (sid >> 3) & 63;
            int sg  = sid & 7;
            const bf16* base = (arr == 0) ? kh : (arr == 1) ? kl : (arr == 2) ? vh : vl;
            cpasync16(sb + AT_OFF_KV + arr * (2 * AT_KVB) + bu * AT_KVB + row * 144 + sg * 16,
                      base + gbase + (size_t)(k0 + row) * CH + sg * 8);
        }
    };

    stageKV(0, 0);
    cp_commit();

    const int lq = lane >> 3, lr = lane & 7;
    const uint32_t aQ = ((wid * 16 + (lq & 1) * 8 + lr) * ATP + (lq >> 1) * 8) * 2;
    const uint32_t kRC = (((lq >> 1) * 8 + lr) * ATP + (lq & 1) * 8) * 2;
    const uint32_t vRC = (((lq & 1) * 8 + lr) * ATP + (lq >> 1) * 8) * 2;

    float of[8][4];
#pragma unroll
    for (int j = 0; j < 8; j++)
#pragma unroll
        for (int c = 0; c < 4; c++) of[j][c] = 0.f;
    float m0 = -1e30f, m1 = -1e30f, l0 = 0.f, l1 = 0.f;

    for (int it = 0; it < 20; it++) {
        const int bu = it & 1;
        if (it + 1 < 20) {
            stageKV(it + 1, bu ^ 1);
            cp_commit();
            cp_wait1();
        } else {
            cp_wait0();
        }
        __syncthreads();

        const uint32_t uKh = sb + AT_OFF_KV + 0 * (2*AT_KVB) + bu * AT_KVB;
        const uint32_t uKl = sb + AT_OFF_KV + 1 * (2*AT_KVB) + bu * AT_KVB;
        const uint32_t uVh = sb + AT_OFF_KV + 2 * (2*AT_KVB) + bu * AT_KVB;
        const uint32_t uVl = sb + AT_OFF_KV + 3 * (2*AT_KVB) + bu * AT_KVB;

        float sf[8][4];
#pragma unroll
        for (int j = 0; j < 8; j++)
#pragma unroll
            for (int c = 0; c < 4; c++) sf[j][c] = 0.f;
#pragma unroll
        for (int s = 0; s < 4; s++) {
            uint32_t aH[4], aL[4];
            ldsm4(aH, sb + aQ + s * 32);
            ldsm4(aL, sb + AT_QBYTES + aQ + s * 32);
#pragma unroll
            for (int ng = 0; ng < 4; ng++) {
                uint32_t koff = kRC + (ng * 16 * ATP + s * 16) * 2;
                uint32_t kb[4], kbl[4];
                ldsm4(kb,  uKh + koff);
                ldsm4(kbl, uKl + koff);
                mma16816(sf[2*ng],   aH, kb);
                mma16816(sf[2*ng+1], aH, kb + 2);
                mma16816(sf[2*ng],   aH, kbl);
                mma16816(sf[2*ng+1], aH, kbl + 2);
                mma16816(sf[2*ng],   aL, kb);
                mma16816(sf[2*ng+1], aL, kb + 2);
            }
        }

        float mloc0 = -1e30f, mloc1 = -1e30f;
#pragma unroll
        for (int j = 0; j < 8; j++) {
#pragma unroll
            for (int c = 0; c < 4; c++) sf[j][c] *= 0.125f;
            mloc0 = fmaxf(mloc0, fmaxf(sf[j][0], sf[j][1]));
            mloc1 = fmaxf(mloc1, fmaxf(sf[j][2], sf[j][3]));
        }
        mloc0 = fmaxf(mloc0, __shfl_xor_sync(0xffffffffu, mloc0, 1));
        mloc0 = fmaxf(mloc0, __shfl_xor_sync(0xffffffffu, mloc0, 2));
        mloc1 = fmaxf(mloc1, __shfl_xor_sync(0xffffffffu, mloc1, 1));
        mloc1 = fmaxf(mloc1, __shfl_xor_sync(0xffffffffu, mloc1, 2));
        float mn0 = fmaxf(m0, mloc0), mn1 = fmaxf(m1, mloc1);
        float al0 = __expf(m0 - mn0), al1 = __expf(m1 - mn1);
        m0 = mn0; m1 = mn1;

        uint32_t php[8], php2[8], plp[8], plp2[8];
        float sum0 = 0.f, sum1 = 0.f;
#pragma unroll
        for (int j = 0; j < 8; j++) {
            float p0 = __expf(sf[j][0] - m0);
            float p1 = __expf(sf[j][1] - m0);
            float p2 = __expf(sf[j][2] - m1);
            float p3 = __expf(sf[j][3] - m1);
            sum0 += p0 + p1; sum1 += p2 + p3;
            uint32_t h0 = pk_bf16(p0, p1), h1 = pk_bf16(p2, p3);
            php[j]  = h0;  php2[j] = h1;
            plp[j]  = pk_bf16(p0 - bf_lo(h0), p1 - bf_hi(h0));
            plp2[j] = pk_bf16(p2 - bf_lo(h1), p3 - bf_hi(h1));
        }
        sum0 += __shfl_xor_sync(0xffffffffu, sum0, 1);
        sum0 += __shfl_xor_sync(0xffffffffu, sum0, 2);
        sum1 += __shfl_xor_sync(0xffffffffu, sum1, 1);
        sum1 += __shfl_xor_sync(0xffffffffu, sum1, 2);
        l0 = l0 * al0 + sum0;
        l1 = l1 * al1 + sum1;
#pragma unroll
        for (int j = 0; j < 8; j++) {
            of[j][0] *= al0; of[j][1] *= al0;
            of[j][2] *= al1; of[j][3] *= al1;
        }

#pragma unroll
        for (int t = 0; t < 4; t++) {
            uint32_t aPh[4] = {php[2*t], php2[2*t], php[2*t+1], php2[2*t+1]};
            uint32_t aPl[4] = {plp[2*t], plp2[2*t], plp[2*t+1], plp2[2*t+1]};
#pragma unroll
            for (int jp = 0; jp < 4; jp++) {
                uint32_t voff = vRC + (t * 16 * ATP + jp * 16) * 2;
                uint32_t vb[4], vbl[4];
                ldsm4t(vb,  uVh + voff);
                ldsm4t(vbl, uVl + voff);
                mma16816(of[2*jp],   aPh, vb);
                mma16816(of[2*jp+1], aPh, vb + 2);
                mma16816(of[2*jp],   aPh, vbl);
                mma16816(of[2*jp+1], aPh, vbl + 2);
                mma16816(of[2*jp],   aPl, vb);
                mma16816(of[2*jp+1], aPl, vb + 2);
            }
        }
        __syncthreads();
    }

    const int gr = lane >> 2, gc = lane & 3;
    const float inv0 = 1.f / l0, inv1 = 1.f / l1;
    const size_t rA = gbase + (size_t)(q0 + wid * 16 + gr) * CH;
    const size_t rB = rA + (size_t)8 * CH;
#pragma unroll
    for (int j = 0; j < 8; j++) {
        float o0 = of[j][0] * inv0, o1 = of[j][1] * inv0;
        float o2 = of[j][2] * inv1, o3 = of[j][3] * inv1;
        uint32_t h0 = pk_bf16(o0, o1), h1 = pk_bf16(o2, o3);
        uint32_t lo0 = pk_bf16(o0 - bf_lo(h0), o1 - bf_hi(h0));
        uint32_t lo1 = pk_bf16(o2 - bf_lo(h1), o3 - bf_hi(h1));
        int c = j * 8 + gc * 2;
        *(uint32_t*)(yh + rA + c) = h0;
        *(uint32_t*)(yl + rA + c) = lo0;
        *(uint32_t*)(yh + rB + c) = h1;
        *(uint32_t*)(yl + rB + c) = lo1;
    }
}

// ---------------- orchestration ----------------
extern "C" void kernel_launch(void* const* d_in, const int* in_sizes, int n_in,
                              void* d_out, int out_size)
{
    const float* img  = (const float*)d_in[0];
    const float* rad  = (const float*)d_in[1];
    const float* pos  = (const float*)d_in[2];
    const float* ln1w = (const float*)d_in[3];
    const float* ln1b = (const float*)d_in[4];
    const float* Wq   = (const float*)d_in[5];
    const float* bq   = (const float*)d_in[6];
    const float* Wk   = (const float*)d_in[7];
    const float* bk   = (const float*)d_in[8];
    const float* Wv   = (const float*)d_in[9];
    const float* bv   = (const float*)d_in[10];
    const float* Wo   = (const float*)d_in[11];
    const float* bo   = (const float*)d_in[12];
    const float* ln2w = (const float*)d_in[13];
    const float* ln2b = (const float*)d_in[14];
    const float* W1   = (const float*)d_in[15];
    const float* b1   = (const float*)d_in[16];
    const float* W2   = (const float*)d_in[17];
    const float* b2   = (const float*)d_in[18];
    const float* lnfw = (const float*)d_in[19];
    const float* lnfb = (const float*)d_in[20];
    float* out = (float*)d_out;

    float *x;
    bf16 *qh, *ql, *kh, *kl, *vh, *vl;
    bf16 *hh, *hl, *yh, *yl, *ffh, *ffl;
    bf16 *wqh, *wql, *wkh, *wkl, *wvh, *wvl, *woh, *wol, *w1h, *w1l, *w2h, *w2l;
    cudaGetSymbolAddress((void**)&x,   g_x);
    cudaGetSymbolAddress((void**)&qh,  g_qh);
    cudaGetSymbolAddress((void**)&ql,  g_ql);
    cudaGetSymbolAddress((void**)&kh,  g_kh);
    cudaGetSymbolAddress((void**)&kl,  g_kl);
    cudaGetSymbolAddress((void**)&vh,  g_vh);
    cudaGetSymbolAddress((void**)&vl,  g_vl);
    cudaGetSymbolAddress((void**)&hh,  g_hh);
    cudaGetSymbolAddress((void**)&hl,  g_hl);
    cudaGetSymbolAddress((void**)&yh,  g_yh);
    cudaGetSymbolAddress((void**)&yl,  g_yl);
    cudaGetSymbolAddress((void**)&ffh, g_ffh);
    cudaGetSymbolAddress((void**)&ffl, g_ffl);
    cudaGetSymbolAddress((void**)&wqh, g_wqh);
    cudaGetSymbolAddress((void**)&wql, g_wql);
    cudaGetSymbolAddress((void**)&wkh, g_wkh);
    cudaGetSymbolAddress((void**)&wkl, g_wkl);
    cudaGetSymbolAddress((void**)&wvh, g_wvh);
    cudaGetSymbolAddress((void**)&wvl, g_wvl);
    cudaGetSymbolAddress((void**)&woh, g_woh);
    cudaGetSymbolAddress((void**)&wol, g_wol);
    cudaGetSymbolAddress((void**)&w1h, g_w1h);
    cudaGetSymbolAddress((void**)&w1l, g_w1l);
    cudaGetSymbolAddress((void**)&w2h, g_w2h);
    cudaGetSymbolAddress((void**)&w2l, g_w2l);

    cudaFuncSetAttribute(attn_mma,
                         cudaFuncAttributeMaxDynamicSharedMemorySize, ATTN_SMEM);
    cudaFuncSetAttribute(qkv_mma,
                         cudaFuncAttributeMaxDynamicSharedMemorySize, GEMM_SMEM);
    cudaFuncSetAttribute(gemm_mma<0, true, false>,
                         cudaFuncAttributeMaxDynamicSharedMemorySize, GEMM_SMEM);
    cudaFuncSetAttribute(gemm_mma<1, false, true>,
                         cudaFuncAttributeMaxDynamicSharedMemorySize, GEMM_SMEM);

    const int ncf = NLAYER * CH * FFDIM;

    // launch 0: all weight splits in one kernel (observability: qkv_mma -> global launch 5)
    wsplit_all<<<dim3(ncf / 1024, 6), 256>>>(
        Wq, Wk, Wv, Wo, W1, W2,
        wqh, wql, wkh, wkl, wvh, wvl, woh, wol, w1h, w1l, w2h, w2l);

    // launch 1: embed (coalesced transpose)
    embed_kernel<<<dim3(TOK / 32, CH / 32, BATCH), 256>>>(img, rad, pos);

    for (int l = 0; l < NLAYER; l++) {
        const size_t wcc = (size_t)l * CH * CH;
        const size_t wcf = (size_t)l * CH * FFDIM;

        ln_kernel<<<MROWS / 8, 256>>>(x, hh, hl, ln1w + l * CH, ln1b + l * CH);

        qkv_mma<<<dim3(12, MROWS / 128), 256, GEMM_SMEM>>>(
            hh, hl,
            wqh + wcc, wql + wcc, wkh + wcc, wkl + wcc, wvh + wcc, wvl + wcc,
            bq + l * CH, bk + l * CH, bv + l * CH,
            qh, ql, kh, kl, vh, vl);

        attn_mma<<<dim3(TOK / 128, NHEAD, BATCH), 256, ATTN_SMEM>>>(
            qh, ql, kh, kl, vh, vl, yh, yl);

        gemm_mma<0, true, false><<<dim3(CH / 128, MROWS / 128), 256, GEMM_SMEM>>>(
            yh, yl, woh + wcc, wol + wcc, bo + l * CH, x, x, nullptr, nullptr, CH, CH);

        ln_kernel<<<MROWS / 8, 256>>>(x, hh, hl, ln2w + l * CH, ln2b + l * CH);

        gemm_mma<1, false, true><<<dim3(FFDIM / 128, MROWS / 128), 256, GEMM_SMEM>>>(
            hh, hl, w1h + wcf, w1l + wcf, b1 + l * FFDIM, nullptr,
            nullptr, ffh, ffl, FFDIM, CH);

        gemm_mma<0, true, false><<<dim3(CH / 128, MROWS / 128), 256, GEMM_SMEM>>>(
            ffh, ffl, w2h + wcf, w2l + wcf, b2 + l * CH, x, x, nullptr, nullptr,
            CH, FFDIM);
    }

    lnf_kernel<<<MROWS / 8, 256>>>(x, out, lnfw, lnfb);
}